// round 14
// baseline (speedup 1.0000x reference)
#include <cuda_runtime.h>
#include <cuda_bf16.h>
#include <math.h>

#define MAXN 100000
#define CAP  128
#define NEG_SLOPE 0.2f
#define BN_EPS 1e-5f
#define RECON_W 0.1f

// ---------------- scratch (device globals) ----------------------------------
__device__ float g_h1 [MAXN * 128];   // x @ W1
__device__ float g_h1p[MAXN * 128];   // after GAT1 + BN + ELU
__device__ float g_h2 [MAXN * 32];    // h1p @ W2
__device__ float g_o2 [MAXN * 32];    // after GAT2 + bias
__device__ float g_rec[MAXN * 32];    // decoder recon (reasoner tail in gat2)
__device__ float g_as1[MAXN * 4];
__device__ float g_ad1[MAXN * 4];
__device__ float g_as2[MAXN];
__device__ float g_ad2[MAXN];
__device__ int   g_deg[MAXN];         // zeroed invariant: reset by k_gat2
__device__ int   g_csr[MAXN * CAP];   // per-dst src lists (bucketed)
__device__ __nv_bfloat16 g_w1hi[128 * 136];  // W1^T bf16 hi, n-major padded
__device__ __nv_bfloat16 g_w1lo[128 * 136];
__device__ __nv_bfloat16 g_w2hi[32 * 136];   // W2^T bf16 hi, n-major padded
__device__ __nv_bfloat16 g_w2lo[32 * 136];

__device__ __forceinline__ unsigned s2u(const void* p) {
    unsigned a;
    asm("{ .reg .u64 t; cvta.to.shared.u64 t, %1; cvt.u32.u64 %0, t; }" : "=r"(a) : "l"(p));
    return a;
}

#define LDSM4(f, addr) \
    asm volatile("ldmatrix.sync.aligned.m8n8.x4.shared.b16 {%0,%1,%2,%3}, [%4];" \
        : "=r"((f)[0]),"=r"((f)[1]),"=r"((f)[2]),"=r"((f)[3]) : "r"(addr))

#define MMA_BF16(dd, a, b0, b1) \
    asm volatile("mma.sync.aligned.m16n8k16.row.col.f32.bf16.bf16.f32 " \
        "{%0,%1,%2,%3}, {%4,%5,%6,%7}, {%8,%9}, {%0,%1,%2,%3};" \
        : "+f"((dd)[0]),"+f"((dd)[1]),"+f"((dd)[2]),"+f"((dd)[3]) \
        : "r"((a)[0]),"r"((a)[1]),"r"((a)[2]),"r"((a)[3]), "r"(b0),"r"(b1))

// ---------------- W1/W2 prep (tiny, runs before gemm1) -----------------------
__global__ void k_prep_w(const float* __restrict__ W1, const float* __restrict__ W2) {
    int b = blockIdx.x;
    if (b < 64) {                       // W1: [128,128] k-major -> [n][136]
        int i = b * 256 + threadIdx.x;
        int k = i >> 7, n = i & 127;
        float v = W1[i];
        __nv_bfloat16 hi = __float2bfloat16(v);
        __nv_bfloat16 lo = __float2bfloat16(v - __bfloat162float(hi));
        g_w1hi[n * 136 + k] = hi;
        g_w1lo[n * 136 + k] = lo;
    } else {                            // W2: [128,32] k-major -> [n][136]
        int i = (b - 64) * 256 + threadIdx.x;
        int k = i >> 5, n = i & 31;
        float v = W2[i];
        __nv_bfloat16 hi = __float2bfloat16(v);
        __nv_bfloat16 lo = __float2bfloat16(v - __bfloat162float(hi));
        g_w2hi[n * 136 + k] = hi;
        g_w2lo[n * 136 + k] = lo;
    }
}

// ============================================================================
// GEMM1 via mma.sync bf16 (3-chain hi/lo) + fused alpha1 + overlapped edge
// fill (tail blocks, cheap). Split-K, 2 phases. 256 threads, 128 rows/CTA.
// ============================================================================
#define SMH_ELE (128 * 72)
#define SM_TOT  (4 * SMH_ELE * 2 + 1024)

__global__ __launch_bounds__(256) void k_gemm1_hmma(
    const float* __restrict__ x,
    const float* __restrict__ avs, const float* __restrict__ avd,
    const int* __restrict__ ei, int N, int E, int nb1)
{
    // ---- tail blocks: edge fill (independent of GEMM) ----
    if (blockIdx.x >= nb1) {
        int e = (blockIdx.x - nb1) * 256 + threadIdx.x;
        if (e < E) {
            int s = ei[e], d = ei[E + e];
            int pos = atomicAdd(&g_deg[d], 1);
            if (pos < CAP) g_csr[d * CAP + pos] = s;
        }
        return;
    }

    extern __shared__ char sm[];
    __nv_bfloat16* Ahi = (__nv_bfloat16*)sm;
    __nv_bfloat16* Alo = Ahi + SMH_ELE;
    __nv_bfloat16* Whi = Alo + SMH_ELE;
    __nv_bfloat16* Wlo = Whi + SMH_ELE;
    float* s_as = (float*)(Wlo + SMH_ELE);
    float* s_ad = s_as + 128;

    int t = threadIdx.x;
    int r0 = blockIdx.x * 128;
    int wid = t >> 5, lane = t & 31;
    int j = lane >> 3, rin = lane & 7;

    if (t < 128) { s_as[t] = avs[t]; s_ad[t] = avd[t]; }

    int arow = t >> 1, ac0 = (t & 1) * 32;
    int gr_s = r0 + arow;
    bool aval = gr_s < N;
    int wn = t >> 1, wk0 = (t & 1) * 32;

    unsigned aOff = ((unsigned)((wid * 16 + (j & 1) * 8 + rin) * 72 + (j >> 1) * 8)) * 2;
    unsigned bOff = ((unsigned)(((j >> 1) * 8 + rin) * 72 + (j & 1) * 8)) * 2;
    unsigned aHiB = s2u(Ahi) + aOff, aLoB = s2u(Alo) + aOff;
    unsigned wHiB = s2u(Whi) + bOff, wLoB = s2u(Wlo) + bOff;

    float d[16][4];
#pragma unroll
    for (int i = 0; i < 16; i++)
#pragma unroll
        for (int q = 0; q < 4; q++) d[i][q] = 0.f;

#pragma unroll 1
    for (int half = 0; half < 2; half++) {
        if (half) __syncthreads();
        {
            const float* xr = x + (size_t)gr_s * 128 + half * 64 + ac0;
#pragma unroll
            for (int c = 0; c < 32; c += 4) {
                float4 v = aval ? *(const float4*)(xr + c) : make_float4(0, 0, 0, 0);
                float f[4] = {v.x, v.y, v.z, v.w};
                __nv_bfloat16 h[4], l[4];
#pragma unroll
                for (int q = 0; q < 4; q++) {
                    h[q] = __float2bfloat16(f[q]);
                    l[q] = __float2bfloat16(f[q] - __bfloat162float(h[q]));
                }
                int eo = arow * 72 + ac0 + c;
                *(__nv_bfloat162*)&Ahi[eo]     = __nv_bfloat162(h[0], h[1]);
                *(__nv_bfloat162*)&Ahi[eo + 2] = __nv_bfloat162(h[2], h[3]);
                *(__nv_bfloat162*)&Alo[eo]     = __nv_bfloat162(l[0], l[1]);
                *(__nv_bfloat162*)&Alo[eo + 2] = __nv_bfloat162(l[2], l[3]);
            }
        }
        {
#pragma unroll
            for (int q = 0; q < 4; q++) {
                int so = wn * 136 + half * 64 + wk0 + q * 8;
                int doff = wn * 72 + wk0 + q * 8;
                *(float4*)&Whi[doff] = *(const float4*)&g_w1hi[so];
                *(float4*)&Wlo[doff] = *(const float4*)&g_w1lo[so];
            }
        }
        __syncthreads();

#pragma unroll
        for (int ks = 0; ks < 4; ks++) {
            unsigned ah[4], al[4];
            LDSM4(ah, aHiB + ks * 32);
            LDSM4(al, aLoB + ks * 32);
#pragma unroll
            for (int p = 0; p < 8; p++) {
                unsigned bh[4], bl[4];
                LDSM4(bh, wHiB + p * 2304 + ks * 32);
                LDSM4(bl, wLoB + p * 2304 + ks * 32);
                MMA_BF16(d[2*p],     ah, bh[0], bh[1]);
                MMA_BF16(d[2*p + 1], ah, bh[2], bh[3]);
                MMA_BF16(d[2*p],     al, bh[0], bh[1]);
                MMA_BF16(d[2*p + 1], al, bh[2], bh[3]);
                MMA_BF16(d[2*p],     ah, bl[0], bl[1]);
                MMA_BF16(d[2*p + 1], ah, bl[2], bl[3]);
            }
        }
    }

    int g = lane >> 2, t4 = lane & 3;
    int rA = r0 + wid * 16 + g, rB = rA + 8;
    float psA[4] = {0,0,0,0}, pdA[4] = {0,0,0,0};
    float psB[4] = {0,0,0,0}, pdB[4] = {0,0,0,0};
#pragma unroll
    for (int nt = 0; nt < 16; nt++) {
        int n0 = nt * 8 + 2 * t4;
        float w0s = s_as[n0], w1s = s_as[n0 + 1];
        float w0d = s_ad[n0], w1d = s_ad[n0 + 1];
        int h = nt >> 2;
        psA[h] = fmaf(d[nt][0], w0s, fmaf(d[nt][1], w1s, psA[h]));
        pdA[h] = fmaf(d[nt][0], w0d, fmaf(d[nt][1], w1d, pdA[h]));
        psB[h] = fmaf(d[nt][2], w0s, fmaf(d[nt][3], w1s, psB[h]));
        pdB[h] = fmaf(d[nt][2], w0d, fmaf(d[nt][3], w1d, pdB[h]));
        if (rA < N) *(float2*)&g_h1[(size_t)rA * 128 + n0] = make_float2(d[nt][0], d[nt][1]);
        if (rB < N) *(float2*)&g_h1[(size_t)rB * 128 + n0] = make_float2(d[nt][2], d[nt][3]);
    }
#pragma unroll
    for (int h = 0; h < 4; h++) {
        psA[h] += __shfl_xor_sync(0xffffffffu, psA[h], 1);
        pdA[h] += __shfl_xor_sync(0xffffffffu, pdA[h], 1);
        psB[h] += __shfl_xor_sync(0xffffffffu, psB[h], 1);
        pdB[h] += __shfl_xor_sync(0xffffffffu, pdB[h], 1);
        psA[h] += __shfl_xor_sync(0xffffffffu, psA[h], 2);
        pdA[h] += __shfl_xor_sync(0xffffffffu, pdA[h], 2);
        psB[h] += __shfl_xor_sync(0xffffffffu, psB[h], 2);
        pdB[h] += __shfl_xor_sync(0xffffffffu, pdB[h], 2);
    }
    if (t4 == 0) {
        if (rA < N) {
#pragma unroll
            for (int h = 0; h < 4; h++) { g_as1[rA*4 + h] = psA[h]; g_ad1[rA*4 + h] = pdA[h]; }
        }
        if (rB < N) {
#pragma unroll
            for (int h = 0; h < 4; h++) { g_as1[rB*4 + h] = psB[h]; g_ad1[rB*4 + h] = pdB[h]; }
        }
    }
}

// ============================================================================
// GEMM2 via mma.sync bf16 (3-chain hi/lo) + fused alpha2. 64 rows/CTA.
// Split-K 2 phases, smem ~29KB (round-10 proven config).
// ============================================================================
#define SM2A_ELE (64 * 72)
#define SM2W_ELE (32 * 72)
#define SM2_TOT  (2 * SM2A_ELE * 2 + 2 * SM2W_ELE * 2 + 2 * 32 * 4 + 2 * 128 * 4)

__global__ __launch_bounds__(256) void k_gemm2_hmma(
    const float* __restrict__ avs, const float* __restrict__ avd, int N)
{
    extern __shared__ char sm[];
    __nv_bfloat16* Ahi = (__nv_bfloat16*)sm;
    __nv_bfloat16* Alo = Ahi + SM2A_ELE;
    __nv_bfloat16* Whi = Alo + SM2A_ELE;
    __nv_bfloat16* Wlo = Whi + SM2W_ELE;
    float* s_as = (float*)(Wlo + SM2W_ELE);
    float* s_ad = s_as + 32;
    float* ps_part = s_ad + 32;        // [64][2]
    float* pd_part = ps_part + 128;    // [64][2]

    int t = threadIdx.x;
    int r0 = blockIdx.x * 64;
    int wid = t >> 5, lane = t & 31;
    int j = lane >> 3, rin = lane & 7;

    if (t < 32) { s_as[t] = avs[t]; s_ad[t] = avd[t]; }

    int arow = t >> 2, ac0 = (t & 3) * 16;
    int gr_s = r0 + arow;
    bool aval = gr_s < N;
    int wn = t >> 3, wk0 = (t & 7) * 8;

    unsigned aOff = ((unsigned)(((wid >> 1) * 16 + (j & 1) * 8 + rin) * 72 + (j >> 1) * 8)) * 2;
    unsigned bOff = ((unsigned)(((wid & 1) * 16 + (j >> 1) * 8 + rin) * 72 + (j & 1) * 8)) * 2;
    unsigned aHiB = s2u(Ahi) + aOff, aLoB = s2u(Alo) + aOff;
    unsigned wHiB = s2u(Whi) + bOff, wLoB = s2u(Wlo) + bOff;

    float d[2][4];
#pragma unroll
    for (int i = 0; i < 2; i++)
#pragma unroll
        for (int q = 0; q < 4; q++) d[i][q] = 0.f;

#pragma unroll 1
    for (int half = 0; half < 2; half++) {
        if (half) __syncthreads();
        {
            const float* xr = g_h1p + (size_t)gr_s * 128 + half * 64 + ac0;
#pragma unroll
            for (int c = 0; c < 16; c += 4) {
                float4 v = aval ? *(const float4*)(xr + c) : make_float4(0, 0, 0, 0);
                float f[4] = {v.x, v.y, v.z, v.w};
                __nv_bfloat16 h[4], l[4];
#pragma unroll
                for (int q = 0; q < 4; q++) {
                    h[q] = __float2bfloat16(f[q]);
                    l[q] = __float2bfloat16(f[q] - __bfloat162float(h[q]));
                }
                int eo = arow * 72 + ac0 + c;
                *(__nv_bfloat162*)&Ahi[eo]     = __nv_bfloat162(h[0], h[1]);
                *(__nv_bfloat162*)&Ahi[eo + 2] = __nv_bfloat162(h[2], h[3]);
                *(__nv_bfloat162*)&Alo[eo]     = __nv_bfloat162(l[0], l[1]);
                *(__nv_bfloat162*)&Alo[eo + 2] = __nv_bfloat162(l[2], l[3]);
            }
        }
        {
            int so = wn * 136 + half * 64 + wk0;
            int doff = wn * 72 + wk0;
            *(float4*)&Whi[doff] = *(const float4*)&g_w2hi[so];
            *(float4*)&Wlo[doff] = *(const float4*)&g_w2lo[so];
        }
        __syncthreads();

#pragma unroll
        for (int ks = 0; ks < 4; ks++) {
            unsigned ah[4], al[4], bh[4], bl[4];
            LDSM4(ah, aHiB + ks * 32);
            LDSM4(al, aLoB + ks * 32);
            LDSM4(bh, wHiB + ks * 32);
            LDSM4(bl, wLoB + ks * 32);
            MMA_BF16(d[0], ah, bh[0], bh[1]);
            MMA_BF16(d[1], ah, bh[2], bh[3]);
            MMA_BF16(d[0], al, bh[0], bh[1]);
            MMA_BF16(d[1], al, bh[2], bh[3]);
            MMA_BF16(d[0], ah, bl[0], bl[1]);
            MMA_BF16(d[1], ah, bl[2], bl[3]);
        }
    }

    int g = lane >> 2, t4 = lane & 3;
    int lA = (wid >> 1) * 16 + g, lB = lA + 8;
    int rA = r0 + lA, rB = r0 + lB;
    int nbase = (wid & 1) * 16;
    float psA = 0.f, pdA = 0.f, psB = 0.f, pdB = 0.f;
#pragma unroll
    for (int nt = 0; nt < 2; nt++) {
        int n0 = nbase + nt * 8 + 2 * t4;
        float w0s = s_as[n0], w1s = s_as[n0 + 1];
        float w0d = s_ad[n0], w1d = s_ad[n0 + 1];
        psA = fmaf(d[nt][0], w0s, fmaf(d[nt][1], w1s, psA));
        pdA = fmaf(d[nt][0], w0d, fmaf(d[nt][1], w1d, pdA));
        psB = fmaf(d[nt][2], w0s, fmaf(d[nt][3], w1s, psB));
        pdB = fmaf(d[nt][2], w0d, fmaf(d[nt][3], w1d, pdB));
        if (rA < N) *(float2*)&g_h2[(size_t)rA * 32 + n0] = make_float2(d[nt][0], d[nt][1]);
        if (rB < N) *(float2*)&g_h2[(size_t)rB * 32 + n0] = make_float2(d[nt][2], d[nt][3]);
    }
    psA += __shfl_xor_sync(0xffffffffu, psA, 1);
    pdA += __shfl_xor_sync(0xffffffffu, pdA, 1);
    psB += __shfl_xor_sync(0xffffffffu, psB, 1);
    pdB += __shfl_xor_sync(0xffffffffu, pdB, 1);
    psA += __shfl_xor_sync(0xffffffffu, psA, 2);
    pdA += __shfl_xor_sync(0xffffffffu, pdA, 2);
    psB += __shfl_xor_sync(0xffffffffu, psB, 2);
    pdB += __shfl_xor_sync(0xffffffffu, pdB, 2);
    if (t4 == 0) {
        int nh = wid & 1;
        ps_part[lA * 2 + nh] = psA;  pd_part[lA * 2 + nh] = pdA;
        ps_part[lB * 2 + nh] = psB;  pd_part[lB * 2 + nh] = pdB;
    }
    __syncthreads();
    if (t < 64) {
        int gr = r0 + t;
        if (gr < N) {
            g_as2[gr] = ps_part[t * 2] + ps_part[t * 2 + 1];
            g_ad2[gr] = pd_part[t * 2] + pd_part[t * 2 + 1];
        }
    }
}

// ---------------- GAT1 gather: warp per dst node -----------------------------
__global__ __launch_bounds__(256) void k_gat1(
    const float* __restrict__ b1,
    const float* __restrict__ bg, const float* __restrict__ bb,
    const float* __restrict__ bm, const float* __restrict__ bv, int N)
{
    int gw   = (blockIdx.x * blockDim.x + threadIdx.x) >> 5;
    int lane = threadIdx.x & 31;
    if (gw >= N) return;
    int d    = gw;
    int head = lane >> 3;

    float adv = __ldg(&g_ad1[d * 4 + head]);

    float ts = __ldg(&g_as1[d * 4 + head]) + adv;
    float wself = __expf(fmaxf(ts, NEG_SLOPE * ts));
    const char* h1b  = (const char*)g_h1 + lane * 16;
    const char* as1b = (const char*)g_as1 + head * 4;
    float4 hv = *(const float4*)(h1b + ((size_t)d << 9));
    float4 acc = make_float4(wself*hv.x, wself*hv.y, wself*hv.z, wself*hv.w);
    float wsum = wself;

    int deg = min(g_deg[d], CAP);
    const int* lst = &g_csr[d * CAP];
    for (int j0 = 0; j0 < deg; j0 += 32) {
        int sid = (j0 + lane < deg) ? lst[j0 + lane] : 0;
        int soff = sid << 9;                 // byte offset into g_h1
        int m = min(32, deg - j0);
#pragma unroll 4
        for (int jj = 0; jj < m; jj++) {
            int off = __shfl_sync(0xffffffffu, soff, jj);
            float av = __ldg((const float*)(as1b + ((unsigned)off >> 5)));
            float tt = av + adv;
            float we = __expf(fmaxf(tt, NEG_SLOPE * tt));
            float4 h = *(const float4*)(h1b + off);
            acc.x = fmaf(we, h.x, acc.x);
            acc.y = fmaf(we, h.y, acc.y);
            acc.z = fmaf(we, h.z, acc.z);
            acc.w = fmaf(we, h.w, acc.w);
            wsum += we;
        }
    }

    float inv = 1.f / wsum;
    float4 bc = *(const float4*)&b1[lane * 4];
    float4 g4 = *(const float4*)&bg[lane * 4];
    float4 b4 = *(const float4*)&bb[lane * 4];
    float4 m4 = *(const float4*)&bm[lane * 4];
    float4 v4 = *(const float4*)&bv[lane * 4];
    float4 o;
    o.x = (acc.x * inv + bc.x - m4.x) * rsqrtf(v4.x + BN_EPS) * g4.x + b4.x;
    o.y = (acc.y * inv + bc.y - m4.y) * rsqrtf(v4.y + BN_EPS) * g4.y + b4.y;
    o.z = (acc.z * inv + bc.z - m4.z) * rsqrtf(v4.z + BN_EPS) * g4.z + b4.z;
    o.w = (acc.w * inv + bc.w - m4.w) * rsqrtf(v4.w + BN_EPS) * g4.w + b4.w;
    o.x = o.x > 0.f ? o.x : expm1f(o.x);
    o.y = o.y > 0.f ? o.y : expm1f(o.y);
    o.z = o.z > 0.f ? o.z : expm1f(o.z);
    o.w = o.w > 0.f ? o.w : expm1f(o.w);
    *(float4*)&g_h1p[(size_t)d * 128 + lane * 4] = o;
}

// ---------------- GAT2 gather + reasoner MLP tail blocks ---------------------
// Blocks [0, nb2): warp-per-dst gather (C=32). Blocks [nb2, ...): reasoner
// MLP (expl -> out tail, recon -> g_rec). No dynamic smem here, so extra
// blocks schedule freely.
__global__ __launch_bounds__(256) void k_gat2(
    const float* __restrict__ b2,
    const float* __restrict__ ctx,
    const float* __restrict__ rw1, const float* __restrict__ rb1,
    const float* __restrict__ rw2, const float* __restrict__ rb2,
    const float* __restrict__ dw,  const float* __restrict__ db,
    float* __restrict__ out, int N, int nb2)
{
    if (blockIdx.x >= nb2) {
        // reasoner: expl = relu(ctx@rw1+rb1)@rw2+rb2 ; recon = expl@dw+db
        __shared__ float sw[2336];
        // rw1 0(192) rb1 192(32) rw2 224(1024) rb2 1248(32) dw 1280(1024) db 2304(32)
        int t = threadIdx.x;
        for (int i = t; i < 192;  i += 256) sw[i]        = rw1[i];
        for (int i = t; i < 32;   i += 256) sw[192 + i]  = rb1[i];
        for (int i = t; i < 1024; i += 256) sw[224 + i]  = rw2[i];
        for (int i = t; i < 32;   i += 256) sw[1248 + i] = rb2[i];
        for (int i = t; i < 1024; i += 256) sw[1280 + i] = dw[i];
        for (int i = t; i < 32;   i += 256) sw[2304 + i] = db[i];
        __syncthreads();
        int n = (blockIdx.x - nb2) * 256 + t;
        if (n >= N) return;
        float c0 = ctx[n * 6 + 0], c1 = ctx[n * 6 + 1], c2 = ctx[n * 6 + 2];
        float c3 = ctx[n * 6 + 3], c4 = ctx[n * 6 + 4], c5 = ctx[n * 6 + 5];
        float t1[32];
#pragma unroll
        for (int jj = 0; jj < 32; jj++) {
            float v = sw[192 + jj];
            v = fmaf(c0, sw[0 * 32 + jj], v);
            v = fmaf(c1, sw[1 * 32 + jj], v);
            v = fmaf(c2, sw[2 * 32 + jj], v);
            v = fmaf(c3, sw[3 * 32 + jj], v);
            v = fmaf(c4, sw[4 * 32 + jj], v);
            v = fmaf(c5, sw[5 * 32 + jj], v);
            t1[jj] = fmaxf(v, 0.f);
        }
        float ex[32];
#pragma unroll
        for (int jj = 0; jj < 32; jj++) {
            float v = sw[1248 + jj];
#pragma unroll
            for (int k = 0; k < 32; k++) v = fmaf(t1[k], sw[224 + k * 32 + jj], v);
            ex[jj] = v;
            out[(size_t)N * 10 + (size_t)n * 32 + jj] = v;
        }
#pragma unroll
        for (int jj = 0; jj < 32; jj++) {
            float rec = sw[2304 + jj];
#pragma unroll
            for (int k = 0; k < 32; k++) rec = fmaf(ex[k], sw[1280 + k * 32 + jj], rec);
            g_rec[(size_t)n * 32 + jj] = rec;
        }
        return;
    }

    int gw   = (blockIdx.x * blockDim.x + threadIdx.x) >> 5;
    int lane = threadIdx.x & 31;
    if (gw >= N) return;
    int d = gw;

    float adv = __ldg(&g_ad2[d]);
    float ts = __ldg(&g_as2[d]) + adv;
    float w = __expf(fmaxf(ts, NEG_SLOPE * ts));
    const char* h2b = (const char*)g_h2 + lane * 4;
    float acc = w * *(const float*)(h2b + ((size_t)d << 7));
    float wsum = w;

    int deg = min(g_deg[d], CAP);
    const int* lst = &g_csr[d * CAP];
    for (int j0 = 0; j0 < deg; j0 += 32) {
        int m = min(32, deg - j0);
        int sid = (lane < m) ? lst[j0 + lane] : 0;
        int soff = sid << 7;
        float tt = __ldg(&g_as2[sid]) + adv;
        float wl = (lane < m) ? __expf(fmaxf(tt, NEG_SLOPE * tt)) : 0.f;
#pragma unroll 4
        for (int jj = 0; jj < m; jj++) {
            int off  = __shfl_sync(0xffffffffu, soff, jj);
            float we = __shfl_sync(0xffffffffu, wl, jj);
            acc = fmaf(we, *(const float*)(h2b + off), acc);
            wsum += we;
        }
    }
    g_o2[(size_t)d * 32 + lane] = acc / wsum + __ldg(&b2[lane]);
    if (lane == 0) g_deg[d] = 0;
}

// ---------------- final: comb = o2 + 0.1*rec -> logits -> log_softmax --------
__global__ void k_final(const float* __restrict__ cw, const float* __restrict__ cb,
                        float* __restrict__ out, int N) {
    __shared__ float sw[330];
    int t = threadIdx.x;
    for (int i = t; i < 320; i += 256) sw[i]       = cw[i];
    for (int i = t; i < 10;  i += 256) sw[320 + i] = cb[i];
    __syncthreads();

    int n = blockIdx.x * 256 + t;
    if (n >= N) return;

    float lg[10];
#pragma unroll
    for (int c = 0; c < 10; c++) lg[c] = sw[320 + c];
#pragma unroll
    for (int j4 = 0; j4 < 8; j4++) {
        float4 o4 = *(const float4*)&g_o2[(size_t)n * 32 + j4 * 4];
        float4 r4 = *(const float4*)&g_rec[(size_t)n * 32 + j4 * 4];
        float cb0 = fmaf(RECON_W, r4.x, o4.x);
        float cb1 = fmaf(RECON_W, r4.y, o4.y);
        float cb2 = fmaf(RECON_W, r4.z, o4.z);
        float cb3 = fmaf(RECON_W, r4.w, o4.w);
#pragma unroll
        for (int c = 0; c < 10; c++) {
            lg[c] = fmaf(cb0, sw[(j4 * 4 + 0) * 10 + c], lg[c]);
            lg[c] = fmaf(cb1, sw[(j4 * 4 + 1) * 10 + c], lg[c]);
            lg[c] = fmaf(cb2, sw[(j4 * 4 + 2) * 10 + c], lg[c]);
            lg[c] = fmaf(cb3, sw[(j4 * 4 + 3) * 10 + c], lg[c]);
        }
    }
    float m = lg[0];
#pragma unroll
    for (int c = 1; c < 10; c++) m = fmaxf(m, lg[c]);
    float sum = 0.f;
#pragma unroll
    for (int c = 0; c < 10; c++) sum += expf(lg[c] - m);
    float lse = m + logf(sum);
#pragma unroll
    for (int c = 0; c < 10; c++) out[(size_t)n * 10 + c] = lg[c] - lse;
}

// ---------------- launch ------------------------------------------------------
extern "C" void kernel_launch(void* const* d_in, const int* in_sizes, int n_in,
                              void* d_out, int out_size) {
    const float* x    = (const float*)d_in[0];
    const int*   ei   = (const int*)  d_in[1];
    const float* ctx  = (const float*)d_in[2];
    const float* W1   = (const float*)d_in[3];
    const float* as1  = (const float*)d_in[4];
    const float* ad1  = (const float*)d_in[5];
    const float* b1   = (const float*)d_in[6];
    const float* bng  = (const float*)d_in[7];
    const float* bnb  = (const float*)d_in[8];
    const float* bnm  = (const float*)d_in[9];
    const float* bnv  = (const float*)d_in[10];
    const float* W2   = (const float*)d_in[11];
    const float* as2  = (const float*)d_in[12];
    const float* ad2  = (const float*)d_in[13];
    const float* b2   = (const float*)d_in[14];
    const float* rw1  = (const float*)d_in[15];
    const float* rb1  = (const float*)d_in[16];
    const float* rw2  = (const float*)d_in[17];
    const float* rb2  = (const float*)d_in[18];
    const float* dw   = (const float*)d_in[19];
    const float* db   = (const float*)d_in[20];
    const float* cw   = (const float*)d_in[21];
    const float* cb   = (const float*)d_in[22];
    float* out = (float*)d_out;

    int N = in_sizes[0] / 128;
    int E = in_sizes[1] / 2;

    static bool attr_set = false;
    if (!attr_set) {
        cudaFuncSetAttribute(k_gemm1_hmma, cudaFuncAttributeMaxDynamicSharedMemorySize, SM_TOT);
        cudaFuncSetAttribute(k_gemm2_hmma, cudaFuncAttributeMaxDynamicSharedMemorySize, SM2_TOT);
        attr_set = true;
    }

    // W prep (tiny), then GEMM1 with overlapped edge fill in tail blocks
    k_prep_w<<<80, 256>>>(W1, W2);
    int nb1 = (N + 127) / 128;
    int nbf = (E + 255) / 256;
    k_gemm1_hmma<<<nb1 + nbf, 256, SM_TOT>>>(x, as1, ad1, ei, N, E, nb1);
    k_gat1<<<(N * 32 + 255) / 256, 256>>>(b1, bng, bnb, bnm, bnv, N);

    // layer 2
    k_gemm2_hmma<<<(N + 63) / 64, 256, SM2_TOT>>>(as2, ad2, N);
    int nb2 = (N * 32 + 255) / 256;
    int nbr = (N + 255) / 256;
    k_gat2<<<nb2 + nbr, 256>>>(b2, ctx, rw1, rb1, rw2, rb2, dw, db, out, N, nb2);

    k_final<<<(N + 255) / 256, 256>>>(cw, cb, out, N);
}

// round 15
// speedup vs baseline: 1.2871x; 1.2871x over previous
#include <cuda_runtime.h>
#include <cuda_bf16.h>
#include <math.h>

#define MAXN 100000
#define CAP  128
#define NEG_SLOPE 0.2f
#define BN_EPS 1e-5f
#define RECON_W 0.1f

// ---------------- scratch (device globals) ----------------------------------
__device__ float g_h1 [MAXN * 128];   // x @ W1
__device__ float g_h1p[MAXN * 128];   // after GAT1 + BN + ELU
__device__ float g_h2 [MAXN * 32];    // h1p @ W2
__device__ float g_o2 [MAXN * 32];    // after GAT2 + bias
__device__ float g_as1[MAXN * 4];
__device__ float g_ad1[MAXN * 4];
__device__ float g_as2[MAXN];
__device__ float g_ad2[MAXN];
__device__ int   g_deg[MAXN];         // zeroed invariant: reset by k_gat2
__device__ int   g_csr[MAXN * CAP];   // per-dst src lists (bucketed)
__device__ __nv_bfloat16 g_w1hi[128 * 136];  // W1^T bf16 hi, n-major padded
__device__ __nv_bfloat16 g_w1lo[128 * 136];
__device__ __nv_bfloat16 g_w2hi[32 * 136];   // W2^T bf16 hi, n-major padded
__device__ __nv_bfloat16 g_w2lo[32 * 136];

__device__ __forceinline__ unsigned s2u(const void* p) {
    unsigned a;
    asm("{ .reg .u64 t; cvta.to.shared.u64 t, %1; cvt.u32.u64 %0, t; }" : "=r"(a) : "l"(p));
    return a;
}

#define LDSM4(f, addr) \
    asm volatile("ldmatrix.sync.aligned.m8n8.x4.shared.b16 {%0,%1,%2,%3}, [%4];" \
        : "=r"((f)[0]),"=r"((f)[1]),"=r"((f)[2]),"=r"((f)[3]) : "r"(addr))

#define MMA_BF16(dd, a, b0, b1) \
    asm volatile("mma.sync.aligned.m16n8k16.row.col.f32.bf16.bf16.f32 " \
        "{%0,%1,%2,%3}, {%4,%5,%6,%7}, {%8,%9}, {%0,%1,%2,%3};" \
        : "+f"((dd)[0]),"+f"((dd)[1]),"+f"((dd)[2]),"+f"((dd)[3]) \
        : "r"((a)[0]),"r"((a)[1]),"r"((a)[2]),"r"((a)[3]), "r"(b0),"r"(b1))

// ---------------- W1 prep (tiny, runs before gemm1; W2 prep in gat1 tails) ---
__global__ void k_prep_w(const float* __restrict__ W1) {
    int i = blockIdx.x * 256 + threadIdx.x;   // W1: [128,128] k-major -> [n][136]
    int k = i >> 7, n = i & 127;
    float v = W1[i];
    __nv_bfloat16 hi = __float2bfloat16(v);
    __nv_bfloat16 lo = __float2bfloat16(v - __bfloat162float(hi));
    g_w1hi[n * 136 + k] = hi;
    g_w1lo[n * 136 + k] = lo;
}

// ============================================================================
// GEMM1 via mma.sync bf16 (3-chain hi/lo) + fused alpha1 + overlapped edge
// fill (tail blocks, cheap). Split-K, 2 phases. 256 threads, 128 rows/CTA.
// ============================================================================
#define SMH_ELE (128 * 72)
#define SM_TOT  (4 * SMH_ELE * 2 + 1024)

__global__ __launch_bounds__(256) void k_gemm1_hmma(
    const float* __restrict__ x,
    const float* __restrict__ avs, const float* __restrict__ avd,
    const int* __restrict__ ei, int N, int E, int nb1)
{
    // ---- tail blocks: edge fill (independent of GEMM) ----
    if (blockIdx.x >= nb1) {
        int e = (blockIdx.x - nb1) * 256 + threadIdx.x;
        if (e < E) {
            int s = ei[e], d = ei[E + e];
            int pos = atomicAdd(&g_deg[d], 1);
            if (pos < CAP) g_csr[d * CAP + pos] = s;
        }
        return;
    }

    extern __shared__ char sm[];
    __nv_bfloat16* Ahi = (__nv_bfloat16*)sm;
    __nv_bfloat16* Alo = Ahi + SMH_ELE;
    __nv_bfloat16* Whi = Alo + SMH_ELE;
    __nv_bfloat16* Wlo = Whi + SMH_ELE;
    float* s_as = (float*)(Wlo + SMH_ELE);
    float* s_ad = s_as + 128;

    int t = threadIdx.x;
    int r0 = blockIdx.x * 128;
    int wid = t >> 5, lane = t & 31;
    int j = lane >> 3, rin = lane & 7;

    if (t < 128) { s_as[t] = avs[t]; s_ad[t] = avd[t]; }

    int arow = t >> 1, ac0 = (t & 1) * 32;
    int gr_s = r0 + arow;
    bool aval = gr_s < N;
    int wn = t >> 1, wk0 = (t & 1) * 32;

    unsigned aOff = ((unsigned)((wid * 16 + (j & 1) * 8 + rin) * 72 + (j >> 1) * 8)) * 2;
    unsigned bOff = ((unsigned)(((j >> 1) * 8 + rin) * 72 + (j & 1) * 8)) * 2;
    unsigned aHiB = s2u(Ahi) + aOff, aLoB = s2u(Alo) + aOff;
    unsigned wHiB = s2u(Whi) + bOff, wLoB = s2u(Wlo) + bOff;

    float d[16][4];
#pragma unroll
    for (int i = 0; i < 16; i++)
#pragma unroll
        for (int q = 0; q < 4; q++) d[i][q] = 0.f;

#pragma unroll 1
    for (int half = 0; half < 2; half++) {
        if (half) __syncthreads();
        {
            const float* xr = x + (size_t)gr_s * 128 + half * 64 + ac0;
#pragma unroll
            for (int c = 0; c < 32; c += 4) {
                float4 v = aval ? *(const float4*)(xr + c) : make_float4(0, 0, 0, 0);
                float f[4] = {v.x, v.y, v.z, v.w};
                __nv_bfloat16 h[4], l[4];
#pragma unroll
                for (int q = 0; q < 4; q++) {
                    h[q] = __float2bfloat16(f[q]);
                    l[q] = __float2bfloat16(f[q] - __bfloat162float(h[q]));
                }
                int eo = arow * 72 + ac0 + c;
                *(__nv_bfloat162*)&Ahi[eo]     = __nv_bfloat162(h[0], h[1]);
                *(__nv_bfloat162*)&Ahi[eo + 2] = __nv_bfloat162(h[2], h[3]);
                *(__nv_bfloat162*)&Alo[eo]     = __nv_bfloat162(l[0], l[1]);
                *(__nv_bfloat162*)&Alo[eo + 2] = __nv_bfloat162(l[2], l[3]);
            }
        }
        {
#pragma unroll
            for (int q = 0; q < 4; q++) {
                int so = wn * 136 + half * 64 + wk0 + q * 8;
                int doff = wn * 72 + wk0 + q * 8;
                *(float4*)&Whi[doff] = *(const float4*)&g_w1hi[so];
                *(float4*)&Wlo[doff] = *(const float4*)&g_w1lo[so];
            }
        }
        __syncthreads();

        // prefetch half-1 x region (one 128B line per thread) into L2 so the
        // inter-phase load is an L2 hit instead of DRAM
        if (half == 0 && aval)
            asm volatile("prefetch.global.L2 [%0];"
                         :: "l"(x + (size_t)gr_s * 128 + 64 + ac0));

#pragma unroll
        for (int ks = 0; ks < 4; ks++) {
            unsigned ah[4], al[4];
            LDSM4(ah, aHiB + ks * 32);
            LDSM4(al, aLoB + ks * 32);
#pragma unroll
            for (int p = 0; p < 8; p++) {
                unsigned bh[4], bl[4];
                LDSM4(bh, wHiB + p * 2304 + ks * 32);
                LDSM4(bl, wLoB + p * 2304 + ks * 32);
                MMA_BF16(d[2*p],     ah, bh[0], bh[1]);
                MMA_BF16(d[2*p + 1], ah, bh[2], bh[3]);
                MMA_BF16(d[2*p],     al, bh[0], bh[1]);
                MMA_BF16(d[2*p + 1], al, bh[2], bh[3]);
                MMA_BF16(d[2*p],     ah, bl[0], bl[1]);
                MMA_BF16(d[2*p + 1], ah, bl[2], bl[3]);
            }
        }
    }

    int g = lane >> 2, t4 = lane & 3;
    int rA = r0 + wid * 16 + g, rB = rA + 8;
    float psA[4] = {0,0,0,0}, pdA[4] = {0,0,0,0};
    float psB[4] = {0,0,0,0}, pdB[4] = {0,0,0,0};
#pragma unroll
    for (int nt = 0; nt < 16; nt++) {
        int n0 = nt * 8 + 2 * t4;
        float w0s = s_as[n0], w1s = s_as[n0 + 1];
        float w0d = s_ad[n0], w1d = s_ad[n0 + 1];
        int h = nt >> 2;
        psA[h] = fmaf(d[nt][0], w0s, fmaf(d[nt][1], w1s, psA[h]));
        pdA[h] = fmaf(d[nt][0], w0d, fmaf(d[nt][1], w1d, pdA[h]));
        psB[h] = fmaf(d[nt][2], w0s, fmaf(d[nt][3], w1s, psB[h]));
        pdB[h] = fmaf(d[nt][2], w0d, fmaf(d[nt][3], w1d, pdB[h]));
        if (rA < N) *(float2*)&g_h1[(size_t)rA * 128 + n0] = make_float2(d[nt][0], d[nt][1]);
        if (rB < N) *(float2*)&g_h1[(size_t)rB * 128 + n0] = make_float2(d[nt][2], d[nt][3]);
    }
#pragma unroll
    for (int h = 0; h < 4; h++) {
        psA[h] += __shfl_xor_sync(0xffffffffu, psA[h], 1);
        pdA[h] += __shfl_xor_sync(0xffffffffu, pdA[h], 1);
        psB[h] += __shfl_xor_sync(0xffffffffu, psB[h], 1);
        pdB[h] += __shfl_xor_sync(0xffffffffu, pdB[h], 1);
        psA[h] += __shfl_xor_sync(0xffffffffu, psA[h], 2);
        pdA[h] += __shfl_xor_sync(0xffffffffu, pdA[h], 2);
        psB[h] += __shfl_xor_sync(0xffffffffu, psB[h], 2);
        pdB[h] += __shfl_xor_sync(0xffffffffu, pdB[h], 2);
    }
    if (t4 == 0) {
        if (rA < N) {
#pragma unroll
            for (int h = 0; h < 4; h++) { g_as1[rA*4 + h] = psA[h]; g_ad1[rA*4 + h] = pdA[h]; }
        }
        if (rB < N) {
#pragma unroll
            for (int h = 0; h < 4; h++) { g_as1[rB*4 + h] = psB[h]; g_ad1[rB*4 + h] = pdB[h]; }
        }
    }
}

// ============================================================================
// GEMM2 via mma.sync bf16 (3-chain hi/lo) + fused alpha2. 64 rows/CTA.
// Split-K 2 phases, smem ~29KB (round-10 proven config).
// ============================================================================
#define SM2A_ELE (64 * 72)
#define SM2W_ELE (32 * 72)
#define SM2_TOT  (2 * SM2A_ELE * 2 + 2 * SM2W_ELE * 2 + 2 * 32 * 4 + 2 * 128 * 4)

__global__ __launch_bounds__(256) void k_gemm2_hmma(
    const float* __restrict__ avs, const float* __restrict__ avd, int N)
{
    extern __shared__ char sm[];
    __nv_bfloat16* Ahi = (__nv_bfloat16*)sm;
    __nv_bfloat16* Alo = Ahi + SM2A_ELE;
    __nv_bfloat16* Whi = Alo + SM2A_ELE;
    __nv_bfloat16* Wlo = Whi + SM2W_ELE;
    float* s_as = (float*)(Wlo + SM2W_ELE);
    float* s_ad = s_as + 32;
    float* ps_part = s_ad + 32;        // [64][2]
    float* pd_part = ps_part + 128;    // [64][2]

    int t = threadIdx.x;
    int r0 = blockIdx.x * 64;
    int wid = t >> 5, lane = t & 31;
    int j = lane >> 3, rin = lane & 7;

    if (t < 32) { s_as[t] = avs[t]; s_ad[t] = avd[t]; }

    int arow = t >> 2, ac0 = (t & 3) * 16;
    int gr_s = r0 + arow;
    bool aval = gr_s < N;
    int wn = t >> 3, wk0 = (t & 7) * 8;

    unsigned aOff = ((unsigned)(((wid >> 1) * 16 + (j & 1) * 8 + rin) * 72 + (j >> 1) * 8)) * 2;
    unsigned bOff = ((unsigned)(((wid & 1) * 16 + (j >> 1) * 8 + rin) * 72 + (j & 1) * 8)) * 2;
    unsigned aHiB = s2u(Ahi) + aOff, aLoB = s2u(Alo) + aOff;
    unsigned wHiB = s2u(Whi) + bOff, wLoB = s2u(Wlo) + bOff;

    float d[2][4];
#pragma unroll
    for (int i = 0; i < 2; i++)
#pragma unroll
        for (int q = 0; q < 4; q++) d[i][q] = 0.f;

#pragma unroll 1
    for (int half = 0; half < 2; half++) {
        if (half) __syncthreads();
        {
            const float* xr = g_h1p + (size_t)gr_s * 128 + half * 64 + ac0;
#pragma unroll
            for (int c = 0; c < 16; c += 4) {
                float4 v = aval ? *(const float4*)(xr + c) : make_float4(0, 0, 0, 0);
                float f[4] = {v.x, v.y, v.z, v.w};
                __nv_bfloat16 h[4], l[4];
#pragma unroll
                for (int q = 0; q < 4; q++) {
                    h[q] = __float2bfloat16(f[q]);
                    l[q] = __float2bfloat16(f[q] - __bfloat162float(h[q]));
                }
                int eo = arow * 72 + ac0 + c;
                *(__nv_bfloat162*)&Ahi[eo]     = __nv_bfloat162(h[0], h[1]);
                *(__nv_bfloat162*)&Ahi[eo + 2] = __nv_bfloat162(h[2], h[3]);
                *(__nv_bfloat162*)&Alo[eo]     = __nv_bfloat162(l[0], l[1]);
                *(__nv_bfloat162*)&Alo[eo + 2] = __nv_bfloat162(l[2], l[3]);
            }
        }
        {
            int so = wn * 136 + half * 64 + wk0;
            int doff = wn * 72 + wk0;
            *(float4*)&Whi[doff] = *(const float4*)&g_w2hi[so];
            *(float4*)&Wlo[doff] = *(const float4*)&g_w2lo[so];
        }
        __syncthreads();

        if (half == 0 && aval)
            asm volatile("prefetch.global.L2 [%0];"
                         :: "l"(g_h1p + (size_t)gr_s * 128 + 64 + ac0));

#pragma unroll
        for (int ks = 0; ks < 4; ks++) {
            unsigned ah[4], al[4], bh[4], bl[4];
            LDSM4(ah, aHiB + ks * 32);
            LDSM4(al, aLoB + ks * 32);
            LDSM4(bh, wHiB + ks * 32);
            LDSM4(bl, wLoB + ks * 32);
            MMA_BF16(d[0], ah, bh[0], bh[1]);
            MMA_BF16(d[1], ah, bh[2], bh[3]);
            MMA_BF16(d[0], al, bh[0], bh[1]);
            MMA_BF16(d[1], al, bh[2], bh[3]);
            MMA_BF16(d[0], ah, bl[0], bl[1]);
            MMA_BF16(d[1], ah, bl[2], bl[3]);
        }
    }

    int g = lane >> 2, t4 = lane & 3;
    int lA = (wid >> 1) * 16 + g, lB = lA + 8;
    int rA = r0 + lA, rB = r0 + lB;
    int nbase = (wid & 1) * 16;
    float psA = 0.f, pdA = 0.f, psB = 0.f, pdB = 0.f;
#pragma unroll
    for (int nt = 0; nt < 2; nt++) {
        int n0 = nbase + nt * 8 + 2 * t4;
        float w0s = s_as[n0], w1s = s_as[n0 + 1];
        float w0d = s_ad[n0], w1d = s_ad[n0 + 1];
        psA = fmaf(d[nt][0], w0s, fmaf(d[nt][1], w1s, psA));
        pdA = fmaf(d[nt][0], w0d, fmaf(d[nt][1], w1d, pdA));
        psB = fmaf(d[nt][2], w0s, fmaf(d[nt][3], w1s, psB));
        pdB = fmaf(d[nt][2], w0d, fmaf(d[nt][3], w1d, pdB));
        if (rA < N) *(float2*)&g_h2[(size_t)rA * 32 + n0] = make_float2(d[nt][0], d[nt][1]);
        if (rB < N) *(float2*)&g_h2[(size_t)rB * 32 + n0] = make_float2(d[nt][2], d[nt][3]);
    }
    psA += __shfl_xor_sync(0xffffffffu, psA, 1);
    pdA += __shfl_xor_sync(0xffffffffu, pdA, 1);
    psB += __shfl_xor_sync(0xffffffffu, psB, 1);
    pdB += __shfl_xor_sync(0xffffffffu, pdB, 1);
    psA += __shfl_xor_sync(0xffffffffu, psA, 2);
    pdA += __shfl_xor_sync(0xffffffffu, pdA, 2);
    psB += __shfl_xor_sync(0xffffffffu, psB, 2);
    pdB += __shfl_xor_sync(0xffffffffu, pdB, 2);
    if (t4 == 0) {
        int nh = wid & 1;
        ps_part[lA * 2 + nh] = psA;  pd_part[lA * 2 + nh] = pdA;
        ps_part[lB * 2 + nh] = psB;  pd_part[lB * 2 + nh] = pdB;
    }
    __syncthreads();
    if (t < 64) {
        int gr = r0 + t;
        if (gr < N) {
            g_as2[gr] = ps_part[t * 2] + ps_part[t * 2 + 1];
            g_ad2[gr] = pd_part[t * 2] + pd_part[t * 2 + 1];
        }
    }
}

// ---------------- GAT1 gather: warp per dst node; W2-prep tail blocks --------
__global__ __launch_bounds__(256) void k_gat1(
    const float* __restrict__ b1,
    const float* __restrict__ bg, const float* __restrict__ bb,
    const float* __restrict__ bm, const float* __restrict__ bv,
    const float* __restrict__ W2, int N, int nbg)
{
    // tail blocks: W2 prep ([128,32] k-major -> [n][136] bf16 hi/lo)
    if (blockIdx.x >= nbg) {
        int i = (blockIdx.x - nbg) * 256 + threadIdx.x;   // 0..4095
        int k = i >> 5, n = i & 31;
        float v = W2[i];
        __nv_bfloat16 hi = __float2bfloat16(v);
        __nv_bfloat16 lo = __float2bfloat16(v - __bfloat162float(hi));
        g_w2hi[n * 136 + k] = hi;
        g_w2lo[n * 136 + k] = lo;
        return;
    }

    int gw   = (blockIdx.x * blockDim.x + threadIdx.x) >> 5;
    int lane = threadIdx.x & 31;
    if (gw >= N) return;
    int d    = gw;
    int head = lane >> 3;

    float adv = __ldg(&g_ad1[d * 4 + head]);

    float ts = __ldg(&g_as1[d * 4 + head]) + adv;
    float wself = __expf(fmaxf(ts, NEG_SLOPE * ts));
    const char* h1b  = (const char*)g_h1 + lane * 16;
    const char* as1b = (const char*)g_as1 + head * 4;
    float4 hv = *(const float4*)(h1b + ((size_t)d << 9));
    float4 acc = make_float4(wself*hv.x, wself*hv.y, wself*hv.z, wself*hv.w);
    float wsum = wself;

    int deg = min(g_deg[d], CAP);
    const int* lst = &g_csr[d * CAP];
    for (int j0 = 0; j0 < deg; j0 += 32) {
        int sid = (j0 + lane < deg) ? lst[j0 + lane] : 0;
        int soff = sid << 9;                 // byte offset into g_h1
        int m = min(32, deg - j0);
#pragma unroll 4
        for (int jj = 0; jj < m; jj++) {
            int off = __shfl_sync(0xffffffffu, soff, jj);
            float av = __ldg((const float*)(as1b + ((unsigned)off >> 5)));
            float tt = av + adv;
            float we = __expf(fmaxf(tt, NEG_SLOPE * tt));
            float4 h = *(const float4*)(h1b + off);
            acc.x = fmaf(we, h.x, acc.x);
            acc.y = fmaf(we, h.y, acc.y);
            acc.z = fmaf(we, h.z, acc.z);
            acc.w = fmaf(we, h.w, acc.w);
            wsum += we;
        }
    }

    float inv = 1.f / wsum;
    float4 bc = *(const float4*)&b1[lane * 4];
    float4 g4 = *(const float4*)&bg[lane * 4];
    float4 b4 = *(const float4*)&bb[lane * 4];
    float4 m4 = *(const float4*)&bm[lane * 4];
    float4 v4 = *(const float4*)&bv[lane * 4];
    float4 o;
    o.x = (acc.x * inv + bc.x - m4.x) * rsqrtf(v4.x + BN_EPS) * g4.x + b4.x;
    o.y = (acc.y * inv + bc.y - m4.y) * rsqrtf(v4.y + BN_EPS) * g4.y + b4.y;
    o.z = (acc.z * inv + bc.z - m4.z) * rsqrtf(v4.z + BN_EPS) * g4.z + b4.z;
    o.w = (acc.w * inv + bc.w - m4.w) * rsqrtf(v4.w + BN_EPS) * g4.w + b4.w;
    o.x = o.x > 0.f ? o.x : expm1f(o.x);
    o.y = o.y > 0.f ? o.y : expm1f(o.y);
    o.z = o.z > 0.f ? o.z : expm1f(o.z);
    o.w = o.w > 0.f ? o.w : expm1f(o.w);
    *(float4*)&g_h1p[(size_t)d * 128 + lane * 4] = o;
}

// ---------------- GAT2 gather: warp per dst node (C=32, 1 head) --------------
__global__ __launch_bounds__(256) void k_gat2(const float* __restrict__ b2, int N) {
    int gw   = (blockIdx.x * blockDim.x + threadIdx.x) >> 5;
    int lane = threadIdx.x & 31;
    if (gw >= N) return;
    int d = gw;

    float adv = __ldg(&g_ad2[d]);
    float ts = __ldg(&g_as2[d]) + adv;
    float w = __expf(fmaxf(ts, NEG_SLOPE * ts));
    const char* h2b = (const char*)g_h2 + lane * 4;
    float acc = w * *(const float*)(h2b + ((size_t)d << 7));
    float wsum = w;

    int deg = min(g_deg[d], CAP);
    const int* lst = &g_csr[d * CAP];
    for (int j0 = 0; j0 < deg; j0 += 32) {
        int m = min(32, deg - j0);
        int sid = (lane < m) ? lst[j0 + lane] : 0;
        int soff = sid << 7;
        float tt = __ldg(&g_as2[sid]) + adv;
        float wl = (lane < m) ? __expf(fmaxf(tt, NEG_SLOPE * tt)) : 0.f;
#pragma unroll 4
        for (int jj = 0; jj < m; jj++) {
            int off  = __shfl_sync(0xffffffffu, soff, jj);
            float we = __shfl_sync(0xffffffffu, wl, jj);
            acc = fmaf(we, *(const float*)(h2b + off), acc);
            wsum += we;
        }
    }
    g_o2[(size_t)d * 32 + lane] = acc / wsum + __ldg(&b2[lane]);
    if (lane == 0) g_deg[d] = 0;
}

// ---------------- final: per-node MLP tail + log_softmax (round-10 form) -----
__global__ void k_final(const float* __restrict__ ctx,
                        const float* __restrict__ rw1, const float* __restrict__ rb1,
                        const float* __restrict__ rw2, const float* __restrict__ rb2,
                        const float* __restrict__ dw,  const float* __restrict__ db,
                        const float* __restrict__ cw,  const float* __restrict__ cb,
                        float* __restrict__ out, int N) {
    __shared__ float sw[2666];
    int t = threadIdx.x;
    for (int i = t; i < 192;  i += 256) sw[i]        = rw1[i];
    for (int i = t; i < 32;   i += 256) sw[192 + i]  = rb1[i];
    for (int i = t; i < 1024; i += 256) sw[224 + i]  = rw2[i];
    for (int i = t; i < 32;   i += 256) sw[1248 + i] = rb2[i];
    for (int i = t; i < 1024; i += 256) sw[1280 + i] = dw[i];
    for (int i = t; i < 32;   i += 256) sw[2304 + i] = db[i];
    for (int i = t; i < 320;  i += 256) sw[2336 + i] = cw[i];
    for (int i = t; i < 10;   i += 256) sw[2656 + i] = cb[i];
    __syncthreads();

    int n = blockIdx.x * 256 + t;
    if (n >= N) return;

    float c0 = ctx[n * 6 + 0], c1 = ctx[n * 6 + 1], c2 = ctx[n * 6 + 2];
    float c3 = ctx[n * 6 + 3], c4 = ctx[n * 6 + 4], c5 = ctx[n * 6 + 5];

    float t1[32];
#pragma unroll
    for (int j = 0; j < 32; j++) {
        float v = sw[192 + j];
        v = fmaf(c0, sw[0 * 32 + j], v);
        v = fmaf(c1, sw[1 * 32 + j], v);
        v = fmaf(c2, sw[2 * 32 + j], v);
        v = fmaf(c3, sw[3 * 32 + j], v);
        v = fmaf(c4, sw[4 * 32 + j], v);
        v = fmaf(c5, sw[5 * 32 + j], v);
        t1[j] = fmaxf(v, 0.f);
    }
    float ex[32];
#pragma unroll
    for (int j = 0; j < 32; j++) {
        float v = sw[1248 + j];
#pragma unroll
        for (int k = 0; k < 32; k++) v = fmaf(t1[k], sw[224 + k * 32 + j], v);
        ex[j] = v;
    }
    float comb[32];
#pragma unroll
    for (int j = 0; j < 32; j++) {
        float rec = sw[2304 + j];
#pragma unroll
        for (int k = 0; k < 32; k++) rec = fmaf(ex[k], sw[1280 + k * 32 + j], rec);
        comb[j] = g_o2[(size_t)n * 32 + j] + RECON_W * rec;
    }
    float lg[10];
#pragma unroll
    for (int c = 0; c < 10; c++) {
        float v = sw[2656 + c];
#pragma unroll
        for (int j = 0; j < 32; j++) v = fmaf(comb[j], sw[2336 + j * 10 + c], v);
        lg[c] = v;
    }
    float m = lg[0];
#pragma unroll
    for (int c = 1; c < 10; c++) m = fmaxf(m, lg[c]);
    float sum = 0.f;
#pragma unroll
    for (int c = 0; c < 10; c++) sum += expf(lg[c] - m);
    float lse = m + logf(sum);
#pragma unroll
    for (int c = 0; c < 10; c++) out[n * 10 + c] = lg[c] - lse;
#pragma unroll
    for (int j = 0; j < 32; j++) out[N * 10 + n * 32 + j] = ex[j];
}

// ---------------- launch ------------------------------------------------------
extern "C" void kernel_launch(void* const* d_in, const int* in_sizes, int n_in,
                              void* d_out, int out_size) {
    const float* x    = (const float*)d_in[0];
    const int*   ei   = (const int*)  d_in[1];
    const float* ctx  = (const float*)d_in[2];
    const float* W1   = (const float*)d_in[3];
    const float* as1  = (const float*)d_in[4];
    const float* ad1  = (const float*)d_in[5];
    const float* b1   = (const float*)d_in[6];
    const float* bng  = (const float*)d_in[7];
    const float* bnb  = (const float*)d_in[8];
    const float* bnm  = (const float*)d_in[9];
    const float* bnv  = (const float*)d_in[10];
    const float* W2   = (const float*)d_in[11];
    const float* as2  = (const float*)d_in[12];
    const float* ad2  = (const float*)d_in[13];
    const float* b2   = (const float*)d_in[14];
    const float* rw1  = (const float*)d_in[15];
    const float* rb1  = (const float*)d_in[16];
    const float* rw2  = (const float*)d_in[17];
    const float* rb2  = (const float*)d_in[18];
    const float* dw   = (const float*)d_in[19];
    const float* db   = (const float*)d_in[20];
    const float* cw   = (const float*)d_in[21];
    const float* cb   = (const float*)d_in[22];
    float* out = (float*)d_out;

    int N = in_sizes[0] / 128;
    int E = in_sizes[1] / 2;

    static bool attr_set = false;
    if (!attr_set) {
        cudaFuncSetAttribute(k_gemm1_hmma, cudaFuncAttributeMaxDynamicSharedMemorySize, SM_TOT);
        cudaFuncSetAttribute(k_gemm2_hmma, cudaFuncAttributeMaxDynamicSharedMemorySize, SM2_TOT);
        attr_set = true;
    }

    // W1 prep (tiny), then GEMM1 with overlapped edge fill in tail blocks
    k_prep_w<<<64, 256>>>(W1);
    int nb1 = (N + 127) / 128;
    int nbf = (E + 255) / 256;
    k_gemm1_hmma<<<nb1 + nbf, 256, SM_TOT>>>(x, as1, ad1, ei, N, E, nb1);
    // GAT1 gather with W2-prep tail blocks (16 trivial blocks)
    int nbg = (N * 32 + 255) / 256;
    k_gat1<<<nbg + 16, 256>>>(b1, bng, bnb, bnm, bnv, W2, N, nbg);

    // layer 2
    k_gemm2_hmma<<<(N + 63) / 64, 256, SM2_TOT>>>(as2, ad2, N);
    k_gat2<<<(N * 32 + 255) / 256, 256>>>(b2, N);

    k_final<<<(N + 255) / 256, 256>>>(ctx, rw1, rb1, rw2, rb2, dw, db, cw, cb,
                                      out, N);
}

// round 16
// speedup vs baseline: 1.8134x; 1.4089x over previous
#include <cuda_runtime.h>
#include <cuda_bf16.h>
#include <math.h>

#define MAXN 100000
#define CAP  128
#define NEG_SLOPE 0.2f
#define BN_EPS 1e-5f
#define RECON_W 0.1f

// ---------------- scratch (device globals) ----------------------------------
__device__ float g_h1 [MAXN * 128];   // x @ W1
__device__ float g_h1p[MAXN * 128];   // after GAT1 + BN + ELU
__device__ float g_h2 [MAXN * 32];    // h1p @ W2
__device__ float g_o2 [MAXN * 32];    // after GAT2 + bias
__device__ float g_as1[MAXN * 4];
__device__ float g_ad1[MAXN * 4];
__device__ float g_as2[MAXN];
__device__ float g_ad2[MAXN];
__device__ int   g_deg[MAXN];         // zeroed invariant: reset by k_gat2
__device__ int   g_csr[MAXN * CAP];   // per-dst src lists (bucketed)
__device__ __nv_bfloat16 g_w1hi[128 * 136];  // W1^T bf16 hi, n-major padded
__device__ __nv_bfloat16 g_w1lo[128 * 136];
__device__ __nv_bfloat16 g_w2hi[32 * 136];   // W2^T bf16 hi, n-major padded
__device__ __nv_bfloat16 g_w2lo[32 * 136];

__device__ __forceinline__ unsigned s2u(const void* p) {
    unsigned a;
    asm("{ .reg .u64 t; cvta.to.shared.u64 t, %1; cvt.u32.u64 %0, t; }" : "=r"(a) : "l"(p));
    return a;
}

#define LDSM4(f, addr) \
    asm volatile("ldmatrix.sync.aligned.m8n8.x4.shared.b16 {%0,%1,%2,%3}, [%4];" \
        : "=r"((f)[0]),"=r"((f)[1]),"=r"((f)[2]),"=r"((f)[3]) : "r"(addr))

#define MMA_BF16(dd, a, b0, b1) \
    asm volatile("mma.sync.aligned.m16n8k16.row.col.f32.bf16.bf16.f32 " \
        "{%0,%1,%2,%3}, {%4,%5,%6,%7}, {%8,%9}, {%0,%1,%2,%3};" \
        : "+f"((dd)[0]),"+f"((dd)[1]),"+f"((dd)[2]),"+f"((dd)[3]) \
        : "r"((a)[0]),"r"((a)[1]),"r"((a)[2]),"r"((a)[3]), "r"(b0),"r"(b1))

// ---------------- W1/W2 prep (tiny, runs before gemm1) -----------------------
__global__ void k_prep_w(const float* __restrict__ W1, const float* __restrict__ W2) {
    int b = blockIdx.x;
    if (b < 64) {                       // W1: [128,128] k-major -> [n][136]
        int i = b * 256 + threadIdx.x;
        int k = i >> 7, n = i & 127;
        float v = W1[i];
        __nv_bfloat16 hi = __float2bfloat16(v);
        __nv_bfloat16 lo = __float2bfloat16(v - __bfloat162float(hi));
        g_w1hi[n * 136 + k] = hi;
        g_w1lo[n * 136 + k] = lo;
    } else {                            // W2: [128,32] k-major -> [n][136]
        int i = (b - 64) * 256 + threadIdx.x;
        int k = i >> 5, n = i & 31;
        float v = W2[i];
        __nv_bfloat16 hi = __float2bfloat16(v);
        __nv_bfloat16 lo = __float2bfloat16(v - __bfloat162float(hi));
        g_w2hi[n * 136 + k] = hi;
        g_w2lo[n * 136 + k] = lo;
    }
}

// ============================================================================
// GEMM1 via mma.sync bf16 (3-chain hi/lo) + fused alpha1 + overlapped edge
// fill (tail blocks). Split-K, 2 phases. 256 threads, 128 rows/CTA.
// ============================================================================
#define SMH_ELE (128 * 72)
#define SM_TOT  (4 * SMH_ELE * 2 + 1024)

__global__ __launch_bounds__(256) void k_gemm1_hmma(
    const float* __restrict__ x,
    const float* __restrict__ avs, const float* __restrict__ avd,
    const int* __restrict__ ei, int N, int E, int nb1)
{
    // ---- tail blocks: edge fill (independent of GEMM) ----
    if (blockIdx.x >= nb1) {
        int e = (blockIdx.x - nb1) * 256 + threadIdx.x;
        if (e < E) {
            int s = ei[e], d = ei[E + e];
            int pos = atomicAdd(&g_deg[d], 1);
            if (pos < CAP) g_csr[d * CAP + pos] = s;
        }
        return;
    }

    extern __shared__ char sm[];
    __nv_bfloat16* Ahi = (__nv_bfloat16*)sm;
    __nv_bfloat16* Alo = Ahi + SMH_ELE;
    __nv_bfloat16* Whi = Alo + SMH_ELE;
    __nv_bfloat16* Wlo = Whi + SMH_ELE;
    float* s_as = (float*)(Wlo + SMH_ELE);
    float* s_ad = s_as + 128;

    int t = threadIdx.x;
    int r0 = blockIdx.x * 128;
    int wid = t >> 5, lane = t & 31;
    int j = lane >> 3, rin = lane & 7;

    if (t < 128) { s_as[t] = avs[t]; s_ad[t] = avd[t]; }

    int arow = t >> 1, ac0 = (t & 1) * 32;
    int gr_s = r0 + arow;
    bool aval = gr_s < N;
    int wn = t >> 1, wk0 = (t & 1) * 32;

    unsigned aOff = ((unsigned)((wid * 16 + (j & 1) * 8 + rin) * 72 + (j >> 1) * 8)) * 2;
    unsigned bOff = ((unsigned)(((j >> 1) * 8 + rin) * 72 + (j & 1) * 8)) * 2;
    unsigned aHiB = s2u(Ahi) + aOff, aLoB = s2u(Alo) + aOff;
    unsigned wHiB = s2u(Whi) + bOff, wLoB = s2u(Wlo) + bOff;

    float d[16][4];
#pragma unroll
    for (int i = 0; i < 16; i++)
#pragma unroll
        for (int q = 0; q < 4; q++) d[i][q] = 0.f;

#pragma unroll 1
    for (int half = 0; half < 2; half++) {
        if (half) __syncthreads();
        {
            const float* xr = x + (size_t)gr_s * 128 + half * 64 + ac0;
#pragma unroll
            for (int c = 0; c < 32; c += 4) {
                float4 v = aval ? *(const float4*)(xr + c) : make_float4(0, 0, 0, 0);
                float f[4] = {v.x, v.y, v.z, v.w};
                __nv_bfloat16 h[4], l[4];
#pragma unroll
                for (int q = 0; q < 4; q++) {
                    h[q] = __float2bfloat16(f[q]);
                    l[q] = __float2bfloat16(f[q] - __bfloat162float(h[q]));
                }
                int eo = arow * 72 + ac0 + c;
                *(__nv_bfloat162*)&Ahi[eo]     = __nv_bfloat162(h[0], h[1]);
                *(__nv_bfloat162*)&Ahi[eo + 2] = __nv_bfloat162(h[2], h[3]);
                *(__nv_bfloat162*)&Alo[eo]     = __nv_bfloat162(l[0], l[1]);
                *(__nv_bfloat162*)&Alo[eo + 2] = __nv_bfloat162(l[2], l[3]);
            }
        }
        {
#pragma unroll
            for (int q = 0; q < 4; q++) {
                int so = wn * 136 + half * 64 + wk0 + q * 8;
                int doff = wn * 72 + wk0 + q * 8;
                *(float4*)&Whi[doff] = *(const float4*)&g_w1hi[so];
                *(float4*)&Wlo[doff] = *(const float4*)&g_w1lo[so];
            }
        }
        __syncthreads();

#pragma unroll
        for (int ks = 0; ks < 4; ks++) {
            unsigned ah[4], al[4];
            LDSM4(ah, aHiB + ks * 32);
            LDSM4(al, aLoB + ks * 32);
#pragma unroll
            for (int p = 0; p < 8; p++) {
                unsigned bh[4], bl[4];
                LDSM4(bh, wHiB + p * 2304 + ks * 32);
                LDSM4(bl, wLoB + p * 2304 + ks * 32);
                MMA_BF16(d[2*p],     ah, bh[0], bh[1]);
                MMA_BF16(d[2*p + 1], ah, bh[2], bh[3]);
                MMA_BF16(d[2*p],     al, bh[0], bh[1]);
                MMA_BF16(d[2*p + 1], al, bh[2], bh[3]);
                MMA_BF16(d[2*p],     ah, bl[0], bl[1]);
                MMA_BF16(d[2*p + 1], ah, bl[2], bl[3]);
            }
        }
    }

    int g = lane >> 2, t4 = lane & 3;
    int rA = r0 + wid * 16 + g, rB = rA + 8;
    float psA[4] = {0,0,0,0}, pdA[4] = {0,0,0,0};
    float psB[4] = {0,0,0,0}, pdB[4] = {0,0,0,0};
#pragma unroll
    for (int nt = 0; nt < 16; nt++) {
        int n0 = nt * 8 + 2 * t4;
        float w0s = s_as[n0], w1s = s_as[n0 + 1];
        float w0d = s_ad[n0], w1d = s_ad[n0 + 1];
        int h = nt >> 2;
        psA[h] = fmaf(d[nt][0], w0s, fmaf(d[nt][1], w1s, psA[h]));
        pdA[h] = fmaf(d[nt][0], w0d, fmaf(d[nt][1], w1d, pdA[h]));
        psB[h] = fmaf(d[nt][2], w0s, fmaf(d[nt][3], w1s, psB[h]));
        pdB[h] = fmaf(d[nt][2], w0d, fmaf(d[nt][3], w1d, pdB[h]));
        if (rA < N) *(float2*)&g_h1[(size_t)rA * 128 + n0] = make_float2(d[nt][0], d[nt][1]);
        if (rB < N) *(float2*)&g_h1[(size_t)rB * 128 + n0] = make_float2(d[nt][2], d[nt][3]);
    }
#pragma unroll
    for (int h = 0; h < 4; h++) {
        psA[h] += __shfl_xor_sync(0xffffffffu, psA[h], 1);
        pdA[h] += __shfl_xor_sync(0xffffffffu, pdA[h], 1);
        psB[h] += __shfl_xor_sync(0xffffffffu, psB[h], 1);
        pdB[h] += __shfl_xor_sync(0xffffffffu, pdB[h], 1);
        psA[h] += __shfl_xor_sync(0xffffffffu, psA[h], 2);
        pdA[h] += __shfl_xor_sync(0xffffffffu, pdA[h], 2);
        psB[h] += __shfl_xor_sync(0xffffffffu, psB[h], 2);
        pdB[h] += __shfl_xor_sync(0xffffffffu, pdB[h], 2);
    }
    if (t4 == 0) {
        if (rA < N) {
#pragma unroll
            for (int h = 0; h < 4; h++) { g_as1[rA*4 + h] = psA[h]; g_ad1[rA*4 + h] = pdA[h]; }
        }
        if (rB < N) {
#pragma unroll
            for (int h = 0; h < 4; h++) { g_as1[rB*4 + h] = psB[h]; g_ad1[rB*4 + h] = pdB[h]; }
        }
    }
}

// ============================================================================
// GEMM2 via mma.sync bf16 (3-chain hi/lo) + fused alpha2. 64 rows/CTA.
// ============================================================================
#define SM2A_ELE (64 * 72)
#define SM2W_ELE (32 * 72)
#define SM2_TOT  (2 * SM2A_ELE * 2 + 2 * SM2W_ELE * 2 + 2 * 32 * 4 + 2 * 128 * 4)

__global__ __launch_bounds__(256) void k_gemm2_hmma(
    const float* __restrict__ avs, const float* __restrict__ avd, int N)
{
    extern __shared__ char sm[];
    __nv_bfloat16* Ahi = (__nv_bfloat16*)sm;
    __nv_bfloat16* Alo = Ahi + SM2A_ELE;
    __nv_bfloat16* Whi = Alo + SM2A_ELE;
    __nv_bfloat16* Wlo = Whi + SM2W_ELE;
    float* s_as = (float*)(Wlo + SM2W_ELE);
    float* s_ad = s_as + 32;
    float* ps_part = s_ad + 32;        // [64][2]
    float* pd_part = ps_part + 128;    // [64][2]

    int t = threadIdx.x;
    int r0 = blockIdx.x * 64;
    int wid = t >> 5, lane = t & 31;
    int j = lane >> 3, rin = lane & 7;

    if (t < 32) { s_as[t] = avs[t]; s_ad[t] = avd[t]; }

    int arow = t >> 2, ac0 = (t & 3) * 16;
    int gr_s = r0 + arow;
    bool aval = gr_s < N;
    int wn = t >> 3, wk0 = (t & 7) * 8;

    unsigned aOff = ((unsigned)(((wid >> 1) * 16 + (j & 1) * 8 + rin) * 72 + (j >> 1) * 8)) * 2;
    unsigned bOff = ((unsigned)(((wid & 1) * 16 + (j >> 1) * 8 + rin) * 72 + (j & 1) * 8)) * 2;
    unsigned aHiB = s2u(Ahi) + aOff, aLoB = s2u(Alo) + aOff;
    unsigned wHiB = s2u(Whi) + bOff, wLoB = s2u(Wlo) + bOff;

    float d[2][4];
#pragma unroll
    for (int i = 0; i < 2; i++)
#pragma unroll
        for (int q = 0; q < 4; q++) d[i][q] = 0.f;

#pragma unroll 1
    for (int half = 0; half < 2; half++) {
        if (half) __syncthreads();
        {
            const float* xr = g_h1p + (size_t)gr_s * 128 + half * 64 + ac0;
#pragma unroll
            for (int c = 0; c < 16; c += 4) {
                float4 v = aval ? *(const float4*)(xr + c) : make_float4(0, 0, 0, 0);
                float f[4] = {v.x, v.y, v.z, v.w};
                __nv_bfloat16 h[4], l[4];
#pragma unroll
                for (int q = 0; q < 4; q++) {
                    h[q] = __float2bfloat16(f[q]);
                    l[q] = __float2bfloat16(f[q] - __bfloat162float(h[q]));
                }
                int eo = arow * 72 + ac0 + c;
                *(__nv_bfloat162*)&Ahi[eo]     = __nv_bfloat162(h[0], h[1]);
                *(__nv_bfloat162*)&Ahi[eo + 2] = __nv_bfloat162(h[2], h[3]);
                *(__nv_bfloat162*)&Alo[eo]     = __nv_bfloat162(l[0], l[1]);
                *(__nv_bfloat162*)&Alo[eo + 2] = __nv_bfloat162(l[2], l[3]);
            }
        }
        {
            int so = wn * 136 + half * 64 + wk0;
            int doff = wn * 72 + wk0;
            *(float4*)&Whi[doff] = *(const float4*)&g_w2hi[so];
            *(float4*)&Wlo[doff] = *(const float4*)&g_w2lo[so];
        }
        __syncthreads();

#pragma unroll
        for (int ks = 0; ks < 4; ks++) {
            unsigned ah[4], al[4], bh[4], bl[4];
            LDSM4(ah, aHiB + ks * 32);
            LDSM4(al, aLoB + ks * 32);
            LDSM4(bh, wHiB + ks * 32);
            LDSM4(bl, wLoB + ks * 32);
            MMA_BF16(d[0], ah, bh[0], bh[1]);
            MMA_BF16(d[1], ah, bh[2], bh[3]);
            MMA_BF16(d[0], al, bh[0], bh[1]);
            MMA_BF16(d[1], al, bh[2], bh[3]);
            MMA_BF16(d[0], ah, bl[0], bl[1]);
            MMA_BF16(d[1], ah, bl[2], bl[3]);
        }
    }

    int g = lane >> 2, t4 = lane & 3;
    int lA = (wid >> 1) * 16 + g, lB = lA + 8;
    int rA = r0 + lA, rB = r0 + lB;
    int nbase = (wid & 1) * 16;
    float psA = 0.f, pdA = 0.f, psB = 0.f, pdB = 0.f;
#pragma unroll
    for (int nt = 0; nt < 2; nt++) {
        int n0 = nbase + nt * 8 + 2 * t4;
        float w0s = s_as[n0], w1s = s_as[n0 + 1];
        float w0d = s_ad[n0], w1d = s_ad[n0 + 1];
        psA = fmaf(d[nt][0], w0s, fmaf(d[nt][1], w1s, psA));
        pdA = fmaf(d[nt][0], w0d, fmaf(d[nt][1], w1d, pdA));
        psB = fmaf(d[nt][2], w0s, fmaf(d[nt][3], w1s, psB));
        pdB = fmaf(d[nt][2], w0d, fmaf(d[nt][3], w1d, pdB));
        if (rA < N) *(float2*)&g_h2[(size_t)rA * 32 + n0] = make_float2(d[nt][0], d[nt][1]);
        if (rB < N) *(float2*)&g_h2[(size_t)rB * 32 + n0] = make_float2(d[nt][2], d[nt][3]);
    }
    psA += __shfl_xor_sync(0xffffffffu, psA, 1);
    pdA += __shfl_xor_sync(0xffffffffu, pdA, 1);
    psB += __shfl_xor_sync(0xffffffffu, psB, 1);
    pdB += __shfl_xor_sync(0xffffffffu, pdB, 1);
    psA += __shfl_xor_sync(0xffffffffu, psA, 2);
    pdA += __shfl_xor_sync(0xffffffffu, pdA, 2);
    psB += __shfl_xor_sync(0xffffffffu, psB, 2);
    pdB += __shfl_xor_sync(0xffffffffu, pdB, 2);
    if (t4 == 0) {
        int nh = wid & 1;
        ps_part[lA * 2 + nh] = psA;  pd_part[lA * 2 + nh] = pdA;
        ps_part[lB * 2 + nh] = psB;  pd_part[lB * 2 + nh] = pdB;
    }
    __syncthreads();
    if (t < 64) {
        int gr = r0 + t;
        if (gr < N) {
            g_as2[gr] = ps_part[t * 2] + ps_part[t * 2 + 1];
            g_ad2[gr] = pd_part[t * 2] + pd_part[t * 2 + 1];
        }
    }
}

// ---------------- GAT1 gather: warp per dst node -----------------------------
__global__ __launch_bounds__(256) void k_gat1(
    const float* __restrict__ b1,
    const float* __restrict__ bg, const float* __restrict__ bb,
    const float* __restrict__ bm, const float* __restrict__ bv, int N)
{
    int gw   = (blockIdx.x * blockDim.x + threadIdx.x) >> 5;
    int lane = threadIdx.x & 31;
    if (gw >= N) return;
    int d    = gw;
    int head = lane >> 3;

    float adv = __ldg(&g_ad1[d * 4 + head]);

    float ts = __ldg(&g_as1[d * 4 + head]) + adv;
    float wself = __expf(fmaxf(ts, NEG_SLOPE * ts));
    const char* h1b  = (const char*)g_h1 + lane * 16;
    const char* as1b = (const char*)g_as1 + head * 4;
    float4 hv = *(const float4*)(h1b + ((size_t)d << 9));
    float4 acc = make_float4(wself*hv.x, wself*hv.y, wself*hv.z, wself*hv.w);
    float wsum = wself;

    int deg = min(g_deg[d], CAP);
    const int* lst = &g_csr[d * CAP];
    for (int j0 = 0; j0 < deg; j0 += 32) {
        int sid = (j0 + lane < deg) ? lst[j0 + lane] : 0;
        int soff = sid << 9;                 // byte offset into g_h1
        int m = min(32, deg - j0);
#pragma unroll 4
        for (int jj = 0; jj < m; jj++) {
            int off = __shfl_sync(0xffffffffu, soff, jj);
            float av = __ldg((const float*)(as1b + ((unsigned)off >> 5)));
            float tt = av + adv;
            float we = __expf(fmaxf(tt, NEG_SLOPE * tt));
            float4 h = *(const float4*)(h1b + off);
            acc.x = fmaf(we, h.x, acc.x);
            acc.y = fmaf(we, h.y, acc.y);
            acc.z = fmaf(we, h.z, acc.z);
            acc.w = fmaf(we, h.w, acc.w);
            wsum += we;
        }
    }

    float inv = 1.f / wsum;
    float4 bc = *(const float4*)&b1[lane * 4];
    float4 g4 = *(const float4*)&bg[lane * 4];
    float4 b4 = *(const float4*)&bb[lane * 4];
    float4 m4 = *(const float4*)&bm[lane * 4];
    float4 v4 = *(const float4*)&bv[lane * 4];
    float4 o;
    o.x = (acc.x * inv + bc.x - m4.x) * rsqrtf(v4.x + BN_EPS) * g4.x + b4.x;
    o.y = (acc.y * inv + bc.y - m4.y) * rsqrtf(v4.y + BN_EPS) * g4.y + b4.y;
    o.z = (acc.z * inv + bc.z - m4.z) * rsqrtf(v4.z + BN_EPS) * g4.z + b4.z;
    o.w = (acc.w * inv + bc.w - m4.w) * rsqrtf(v4.w + BN_EPS) * g4.w + b4.w;
    o.x = o.x > 0.f ? o.x : expm1f(o.x);
    o.y = o.y > 0.f ? o.y : expm1f(o.y);
    o.z = o.z > 0.f ? o.z : expm1f(o.z);
    o.w = o.w > 0.f ? o.w : expm1f(o.w);
    *(float4*)&g_h1p[(size_t)d * 128 + lane * 4] = o;
}

// ---------------- GAT2 gather: warp per dst node (C=32, 1 head) --------------
__global__ __launch_bounds__(256) void k_gat2(const float* __restrict__ b2, int N) {
    int gw   = (blockIdx.x * blockDim.x + threadIdx.x) >> 5;
    int lane = threadIdx.x & 31;
    if (gw >= N) return;
    int d = gw;

    float adv = __ldg(&g_ad2[d]);
    float ts = __ldg(&g_as2[d]) + adv;
    float w = __expf(fmaxf(ts, NEG_SLOPE * ts));
    const char* h2b = (const char*)g_h2 + lane * 4;
    float acc = w * *(const float*)(h2b + ((size_t)d << 7));
    float wsum = w;

    int deg = min(g_deg[d], CAP);
    const int* lst = &g_csr[d * CAP];
    for (int j0 = 0; j0 < deg; j0 += 32) {
        int m = min(32, deg - j0);
        int sid = (lane < m) ? lst[j0 + lane] : 0;
        int soff = sid << 7;
        float tt = __ldg(&g_as2[sid]) + adv;
        float wl = (lane < m) ? __expf(fmaxf(tt, NEG_SLOPE * tt)) : 0.f;
#pragma unroll 4
        for (int jj = 0; jj < m; jj++) {
            int off  = __shfl_sync(0xffffffffu, soff, jj);
            float we = __shfl_sync(0xffffffffu, wl, jj);
            acc = fmaf(we, *(const float*)(h2b + off), acc);
            wsum += we;
        }
    }
    g_o2[(size_t)d * 32 + lane] = acc / wsum + __ldg(&b2[lane]);
    if (lane == 0) g_deg[d] = 0;
}

// ---------------- final: per-node MLP tail + log_softmax ---------------------
__global__ void k_final(const float* __restrict__ ctx,
                        const float* __restrict__ rw1, const float* __restrict__ rb1,
                        const float* __restrict__ rw2, const float* __restrict__ rb2,
                        const float* __restrict__ dw,  const float* __restrict__ db,
                        const float* __restrict__ cw,  const float* __restrict__ cb,
                        float* __restrict__ out, int N) {
    __shared__ float sw[2666];
    int t = threadIdx.x;
    for (int i = t; i < 192;  i += 256) sw[i]        = rw1[i];
    for (int i = t; i < 32;   i += 256) sw[192 + i]  = rb1[i];
    for (int i = t; i < 1024; i += 256) sw[224 + i]  = rw2[i];
    for (int i = t; i < 32;   i += 256) sw[1248 + i] = rb2[i];
    for (int i = t; i < 1024; i += 256) sw[1280 + i] = dw[i];
    for (int i = t; i < 32;   i += 256) sw[2304 + i] = db[i];
    for (int i = t; i < 320;  i += 256) sw[2336 + i] = cw[i];
    for (int i = t; i < 10;   i += 256) sw[2656 + i] = cb[i];
    __syncthreads();

    int n = blockIdx.x * 256 + t;
    if (n >= N) return;

    float c0 = ctx[n * 6 + 0], c1 = ctx[n * 6 + 1], c2 = ctx[n * 6 + 2];
    float c3 = ctx[n * 6 + 3], c4 = ctx[n * 6 + 4], c5 = ctx[n * 6 + 5];

    float t1[32];
#pragma unroll
    for (int j = 0; j < 32; j++) {
        float v = sw[192 + j];
        v = fmaf(c0, sw[0 * 32 + j], v);
        v = fmaf(c1, sw[1 * 32 + j], v);
        v = fmaf(c2, sw[2 * 32 + j], v);
        v = fmaf(c3, sw[3 * 32 + j], v);
        v = fmaf(c4, sw[4 * 32 + j], v);
        v = fmaf(c5, sw[5 * 32 + j], v);
        t1[j] = fmaxf(v, 0.f);
    }
    float ex[32];
#pragma unroll
    for (int j = 0; j < 32; j++) {
        float v = sw[1248 + j];
#pragma unroll
        for (int k = 0; k < 32; k++) v = fmaf(t1[k], sw[224 + k * 32 + j], v);
        ex[j] = v;
    }
    float comb[32];
#pragma unroll
    for (int j = 0; j < 32; j++) {
        float rec = sw[2304 + j];
#pragma unroll
        for (int k = 0; k < 32; k++) rec = fmaf(ex[k], sw[1280 + k * 32 + j], rec);
        comb[j] = g_o2[(size_t)n * 32 + j] + RECON_W * rec;
    }
    float lg[10];
#pragma unroll
    for (int c = 0; c < 10; c++) {
        float v = sw[2656 + c];
#pragma unroll
        for (int j = 0; j < 32; j++) v = fmaf(comb[j], sw[2336 + j * 10 + c], v);
        lg[c] = v;
    }
    float m = lg[0];
#pragma unroll
    for (int c = 1; c < 10; c++) m = fmaxf(m, lg[c]);
    float sum = 0.f;
#pragma unroll
    for (int c = 0; c < 10; c++) sum += expf(lg[c] - m);
    float lse = m + logf(sum);
#pragma unroll
    for (int c = 0; c < 10; c++) out[n * 10 + c] = lg[c] - lse;
#pragma unroll
    for (int j = 0; j < 32; j++) out[N * 10 + n * 32 + j] = ex[j];
}

// ---------------- launch ------------------------------------------------------
extern "C" void kernel_launch(void* const* d_in, const int* in_sizes, int n_in,
                              void* d_out, int out_size) {
    const float* x    = (const float*)d_in[0];
    const int*   ei   = (const int*)  d_in[1];
    const float* ctx  = (const float*)d_in[2];
    const float* W1   = (const float*)d_in[3];
    const float* as1  = (const float*)d_in[4];
    const float* ad1  = (const float*)d_in[5];
    const float* b1   = (const float*)d_in[6];
    const float* bng  = (const float*)d_in[7];
    const float* bnb  = (const float*)d_in[8];
    const float* bnm  = (const float*)d_in[9];
    const float* bnv  = (const float*)d_in[10];
    const float* W2   = (const float*)d_in[11];
    const float* as2  = (const float*)d_in[12];
    const float* ad2  = (const float*)d_in[13];
    const float* b2   = (const float*)d_in[14];
    const float* rw1  = (const float*)d_in[15];
    const float* rb1  = (const float*)d_in[16];
    const float* rw2  = (const float*)d_in[17];
    const float* rb2  = (const float*)d_in[18];
    const float* dw   = (const float*)d_in[19];
    const float* db   = (const float*)d_in[20];
    const float* cw   = (const float*)d_in[21];
    const float* cb   = (const float*)d_in[22];
    float* out = (float*)d_out;

    int N = in_sizes[0] / 128;
    int E = in_sizes[1] / 2;

    static bool attr_set = false;
    if (!attr_set) {
        cudaFuncSetAttribute(k_gemm1_hmma, cudaFuncAttributeMaxDynamicSharedMemorySize, SM_TOT);
        cudaFuncSetAttribute(k_gemm2_hmma, cudaFuncAttributeMaxDynamicSharedMemorySize, SM2_TOT);
        attr_set = true;
    }

    // W prep (tiny), then GEMM1 with overlapped edge fill in tail blocks
    k_prep_w<<<80, 256>>>(W1, W2);
    int nb1 = (N + 127) / 128;
    int nbf = (E + 255) / 256;
    k_gemm1_hmma<<<nb1 + nbf, 256, SM_TOT>>>(x, as1, ad1, ei, N, E, nb1);
    k_gat1<<<(N * 32 + 255) / 256, 256>>>(b1, bng, bnb, bnm, bnv, N);

    // layer 2
    k_gemm2_hmma<<<(N + 63) / 64, 256, SM2_TOT>>>(as2, ad2, N);
    k_gat2<<<(N * 32 + 255) / 256, 256>>>(b2, N);

    k_final<<<(N + 255) / 256, 256>>>(ctx, rw1, rb1, rw2, rb2, dw, db, cw, cb,
                                      out, N);
}

// round 17
// speedup vs baseline: 1.8878x; 1.0410x over previous
#include <cuda_runtime.h>
#include <cuda_bf16.h>
#include <math.h>

#define MAXN 100000
#define CAP  128
#define NEG_SLOPE 0.2f
#define BN_EPS 1e-5f
#define RECON_W 0.1f

// ---------------- scratch (device globals) ----------------------------------
__device__ float g_h1 [MAXN * 128];   // x @ W1
__device__ float g_h1p[MAXN * 128];   // after GAT1 + BN + ELU
__device__ float g_h2 [MAXN * 32];    // h1p @ W2
__device__ float g_o2 [MAXN * 32];    // after GAT2 + bias
__device__ float g_as1[MAXN * 4];
__device__ float g_ad1[MAXN * 4];
__device__ float g_as2[MAXN];
__device__ float g_ad2[MAXN];
__device__ int   g_deg[MAXN];         // zeroed invariant: reset by k_gat2
__device__ int   g_csr[MAXN * CAP];   // per-dst src lists (bucketed)
__device__ __nv_bfloat16 g_w1hi[128 * 136];  // W1^T bf16 hi, n-major padded
__device__ __nv_bfloat16 g_w1lo[128 * 136];
__device__ __nv_bfloat16 g_w2hi[32 * 136];   // W2^T bf16 hi, n-major padded
__device__ __nv_bfloat16 g_w2lo[32 * 136];

__device__ __forceinline__ unsigned s2u(const void* p) {
    unsigned a;
    asm("{ .reg .u64 t; cvta.to.shared.u64 t, %1; cvt.u32.u64 %0, t; }" : "=r"(a) : "l"(p));
    return a;
}

#define LDSM4(f, addr) \
    asm volatile("ldmatrix.sync.aligned.m8n8.x4.shared.b16 {%0,%1,%2,%3}, [%4];" \
        : "=r"((f)[0]),"=r"((f)[1]),"=r"((f)[2]),"=r"((f)[3]) : "r"(addr))

#define MMA_BF16(dd, a, b0, b1) \
    asm volatile("mma.sync.aligned.m16n8k16.row.col.f32.bf16.bf16.f32 " \
        "{%0,%1,%2,%3}, {%4,%5,%6,%7}, {%8,%9}, {%0,%1,%2,%3};" \
        : "+f"((dd)[0]),"+f"((dd)[1]),"+f"((dd)[2]),"+f"((dd)[3]) \
        : "r"((a)[0]),"r"((a)[1]),"r"((a)[2]),"r"((a)[3]), "r"(b0),"r"(b1))

// ---------------- W1/W2 prep (tiny, runs before gemm1) -----------------------
__global__ void k_prep_w(const float* __restrict__ W1, const float* __restrict__ W2) {
    int b = blockIdx.x;
    if (b < 64) {                       // W1: [128,128] k-major -> [n][136]
        int i = b * 256 + threadIdx.x;
        int k = i >> 7, n = i & 127;
        float v = W1[i];
        __nv_bfloat16 hi = __float2bfloat16(v);
        __nv_bfloat16 lo = __float2bfloat16(v - __bfloat162float(hi));
        g_w1hi[n * 136 + k] = hi;
        g_w1lo[n * 136 + k] = lo;
    } else {                            // W2: [128,32] k-major -> [n][136]
        int i = (b - 64) * 256 + threadIdx.x;
        int k = i >> 5, n = i & 31;
        float v = W2[i];
        __nv_bfloat16 hi = __float2bfloat16(v);
        __nv_bfloat16 lo = __float2bfloat16(v - __bfloat162float(hi));
        g_w2hi[n * 136 + k] = hi;
        g_w2lo[n * 136 + k] = lo;
    }
}

// ============================================================================
// GEMM1 via mma.sync bf16 (3-chain hi/lo) + fused alpha1 + overlapped edge
// fill (tail blocks). Split-K, 2 phases. 256 threads, 128 rows/CTA.
// ============================================================================
#define SMH_ELE (128 * 72)
#define SM_TOT  (4 * SMH_ELE * 2 + 1024)

__global__ __launch_bounds__(256) void k_gemm1_hmma(
    const float* __restrict__ x,
    const float* __restrict__ avs, const float* __restrict__ avd,
    const int* __restrict__ ei, int N, int E, int nb1)
{
    // ---- tail blocks: edge fill (independent of GEMM) ----
    if (blockIdx.x >= nb1) {
        int e = (blockIdx.x - nb1) * 256 + threadIdx.x;
        if (e < E) {
            int s = ei[e], d = ei[E + e];
            int pos = atomicAdd(&g_deg[d], 1);
            if (pos < CAP) g_csr[d * CAP + pos] = s;
        }
        return;
    }

    extern __shared__ char sm[];
    __nv_bfloat16* Ahi = (__nv_bfloat16*)sm;
    __nv_bfloat16* Alo = Ahi + SMH_ELE;
    __nv_bfloat16* Whi = Alo + SMH_ELE;
    __nv_bfloat16* Wlo = Whi + SMH_ELE;
    float* s_as = (float*)(Wlo + SMH_ELE);
    float* s_ad = s_as + 128;

    int t = threadIdx.x;
    int r0 = blockIdx.x * 128;
    int wid = t >> 5, lane = t & 31;
    int j = lane >> 3, rin = lane & 7;

    if (t < 128) { s_as[t] = avs[t]; s_ad[t] = avd[t]; }

    int arow = t >> 1, ac0 = (t & 1) * 32;
    int gr_s = r0 + arow;
    bool aval = gr_s < N;
    int wn = t >> 1, wk0 = (t & 1) * 32;

    unsigned aOff = ((unsigned)((wid * 16 + (j & 1) * 8 + rin) * 72 + (j >> 1) * 8)) * 2;
    unsigned bOff = ((unsigned)(((j >> 1) * 8 + rin) * 72 + (j & 1) * 8)) * 2;
    unsigned aHiB = s2u(Ahi) + aOff, aLoB = s2u(Alo) + aOff;
    unsigned wHiB = s2u(Whi) + bOff, wLoB = s2u(Wlo) + bOff;

    float d[16][4];
#pragma unroll
    for (int i = 0; i < 16; i++)
#pragma unroll
        for (int q = 0; q < 4; q++) d[i][q] = 0.f;

#pragma unroll 1
    for (int half = 0; half < 2; half++) {
        if (half) __syncthreads();
        {
            const float* xr = x + (size_t)gr_s * 128 + half * 64 + ac0;
#pragma unroll
            for (int c = 0; c < 32; c += 4) {
                float4 v = aval ? *(const float4*)(xr + c) : make_float4(0, 0, 0, 0);
                float f[4] = {v.x, v.y, v.z, v.w};
                __nv_bfloat16 h[4], l[4];
#pragma unroll
                for (int q = 0; q < 4; q++) {
                    h[q] = __float2bfloat16(f[q]);
                    l[q] = __float2bfloat16(f[q] - __bfloat162float(h[q]));
                }
                int eo = arow * 72 + ac0 + c;
                *(__nv_bfloat162*)&Ahi[eo]     = __nv_bfloat162(h[0], h[1]);
                *(__nv_bfloat162*)&Ahi[eo + 2] = __nv_bfloat162(h[2], h[3]);
                *(__nv_bfloat162*)&Alo[eo]     = __nv_bfloat162(l[0], l[1]);
                *(__nv_bfloat162*)&Alo[eo + 2] = __nv_bfloat162(l[2], l[3]);
            }
        }
        {
#pragma unroll
            for (int q = 0; q < 4; q++) {
                int so = wn * 136 + half * 64 + wk0 + q * 8;
                int doff = wn * 72 + wk0 + q * 8;
                *(float4*)&Whi[doff] = *(const float4*)&g_w1hi[so];
                *(float4*)&Wlo[doff] = *(const float4*)&g_w1lo[so];
            }
        }
        __syncthreads();

#pragma unroll
        for (int ks = 0; ks < 4; ks++) {
            unsigned ah[4], al[4];
            LDSM4(ah, aHiB + ks * 32);
            LDSM4(al, aLoB + ks * 32);
#pragma unroll
            for (int p = 0; p < 8; p++) {
                unsigned bh[4], bl[4];
                LDSM4(bh, wHiB + p * 2304 + ks * 32);
                LDSM4(bl, wLoB + p * 2304 + ks * 32);
                MMA_BF16(d[2*p],     ah, bh[0], bh[1]);
                MMA_BF16(d[2*p + 1], ah, bh[2], bh[3]);
                MMA_BF16(d[2*p],     al, bh[0], bh[1]);
                MMA_BF16(d[2*p + 1], al, bh[2], bh[3]);
                MMA_BF16(d[2*p],     ah, bl[0], bl[1]);
                MMA_BF16(d[2*p + 1], ah, bl[2], bl[3]);
            }
        }
    }

    int g = lane >> 2, t4 = lane & 3;
    int rA = r0 + wid * 16 + g, rB = rA + 8;
    float psA[4] = {0,0,0,0}, pdA[4] = {0,0,0,0};
    float psB[4] = {0,0,0,0}, pdB[4] = {0,0,0,0};
#pragma unroll
    for (int nt = 0; nt < 16; nt++) {
        int n0 = nt * 8 + 2 * t4;
        float w0s = s_as[n0], w1s = s_as[n0 + 1];
        float w0d = s_ad[n0], w1d = s_ad[n0 + 1];
        int h = nt >> 2;
        psA[h] = fmaf(d[nt][0], w0s, fmaf(d[nt][1], w1s, psA[h]));
        pdA[h] = fmaf(d[nt][0], w0d, fmaf(d[nt][1], w1d, pdA[h]));
        psB[h] = fmaf(d[nt][2], w0s, fmaf(d[nt][3], w1s, psB[h]));
        pdB[h] = fmaf(d[nt][2], w0d, fmaf(d[nt][3], w1d, pdB[h]));
        if (rA < N) *(float2*)&g_h1[(size_t)rA * 128 + n0] = make_float2(d[nt][0], d[nt][1]);
        if (rB < N) *(float2*)&g_h1[(size_t)rB * 128 + n0] = make_float2(d[nt][2], d[nt][3]);
    }
#pragma unroll
    for (int h = 0; h < 4; h++) {
        psA[h] += __shfl_xor_sync(0xffffffffu, psA[h], 1);
        pdA[h] += __shfl_xor_sync(0xffffffffu, pdA[h], 1);
        psB[h] += __shfl_xor_sync(0xffffffffu, psB[h], 1);
        pdB[h] += __shfl_xor_sync(0xffffffffu, pdB[h], 1);
        psA[h] += __shfl_xor_sync(0xffffffffu, psA[h], 2);
        pdA[h] += __shfl_xor_sync(0xffffffffu, pdA[h], 2);
        psB[h] += __shfl_xor_sync(0xffffffffu, psB[h], 2);
        pdB[h] += __shfl_xor_sync(0xffffffffu, pdB[h], 2);
    }
    if (t4 == 0) {
        if (rA < N) {
#pragma unroll
            for (int h = 0; h < 4; h++) { g_as1[rA*4 + h] = psA[h]; g_ad1[rA*4 + h] = pdA[h]; }
        }
        if (rB < N) {
#pragma unroll
            for (int h = 0; h < 4; h++) { g_as1[rB*4 + h] = psB[h]; g_ad1[rB*4 + h] = pdB[h]; }
        }
    }
}

// ============================================================================
// GEMM2 via mma.sync bf16 (3-chain hi/lo) + fused alpha2. 64 rows/CTA.
// ============================================================================
#define SM2A_ELE (64 * 72)
#define SM2W_ELE (32 * 72)
#define SM2_TOT  (2 * SM2A_ELE * 2 + 2 * SM2W_ELE * 2 + 2 * 32 * 4 + 2 * 128 * 4)

__global__ __launch_bounds__(256) void k_gemm2_hmma(
    const float* __restrict__ avs, const float* __restrict__ avd, int N)
{
    extern __shared__ char sm[];
    __nv_bfloat16* Ahi = (__nv_bfloat16*)sm;
    __nv_bfloat16* Alo = Ahi + SM2A_ELE;
    __nv_bfloat16* Whi = Alo + SM2A_ELE;
    __nv_bfloat16* Wlo = Whi + SM2W_ELE;
    float* s_as = (float*)(Wlo + SM2W_ELE);
    float* s_ad = s_as + 32;
    float* ps_part = s_ad + 32;        // [64][2]
    float* pd_part = ps_part + 128;    // [64][2]

    int t = threadIdx.x;
    int r0 = blockIdx.x * 64;
    int wid = t >> 5, lane = t & 31;
    int j = lane >> 3, rin = lane & 7;

    if (t < 32) { s_as[t] = avs[t]; s_ad[t] = avd[t]; }

    int arow = t >> 2, ac0 = (t & 3) * 16;
    int gr_s = r0 + arow;
    bool aval = gr_s < N;
    int wn = t >> 3, wk0 = (t & 7) * 8;

    unsigned aOff = ((unsigned)(((wid >> 1) * 16 + (j & 1) * 8 + rin) * 72 + (j >> 1) * 8)) * 2;
    unsigned bOff = ((unsigned)(((wid & 1) * 16 + (j >> 1) * 8 + rin) * 72 + (j & 1) * 8)) * 2;
    unsigned aHiB = s2u(Ahi) + aOff, aLoB = s2u(Alo) + aOff;
    unsigned wHiB = s2u(Whi) + bOff, wLoB = s2u(Wlo) + bOff;

    float d[2][4];
#pragma unroll
    for (int i = 0; i < 2; i++)
#pragma unroll
        for (int q = 0; q < 4; q++) d[i][q] = 0.f;

#pragma unroll 1
    for (int half = 0; half < 2; half++) {
        if (half) __syncthreads();
        {
            const float* xr = g_h1p + (size_t)gr_s * 128 + half * 64 + ac0;
#pragma unroll
            for (int c = 0; c < 16; c += 4) {
                float4 v = aval ? *(const float4*)(xr + c) : make_float4(0, 0, 0, 0);
                float f[4] = {v.x, v.y, v.z, v.w};
                __nv_bfloat16 h[4], l[4];
#pragma unroll
                for (int q = 0; q < 4; q++) {
                    h[q] = __float2bfloat16(f[q]);
                    l[q] = __float2bfloat16(f[q] - __bfloat162float(h[q]));
                }
                int eo = arow * 72 + ac0 + c;
                *(__nv_bfloat162*)&Ahi[eo]     = __nv_bfloat162(h[0], h[1]);
                *(__nv_bfloat162*)&Ahi[eo + 2] = __nv_bfloat162(h[2], h[3]);
                *(__nv_bfloat162*)&Alo[eo]     = __nv_bfloat162(l[0], l[1]);
                *(__nv_bfloat162*)&Alo[eo + 2] = __nv_bfloat162(l[2], l[3]);
            }
        }
        {
            int so = wn * 136 + half * 64 + wk0;
            int doff = wn * 72 + wk0;
            *(float4*)&Whi[doff] = *(const float4*)&g_w2hi[so];
            *(float4*)&Wlo[doff] = *(const float4*)&g_w2lo[so];
        }
        __syncthreads();

#pragma unroll
        for (int ks = 0; ks < 4; ks++) {
            unsigned ah[4], al[4], bh[4], bl[4];
            LDSM4(ah, aHiB + ks * 32);
            LDSM4(al, aLoB + ks * 32);
            LDSM4(bh, wHiB + ks * 32);
            LDSM4(bl, wLoB + ks * 32);
            MMA_BF16(d[0], ah, bh[0], bh[1]);
            MMA_BF16(d[1], ah, bh[2], bh[3]);
            MMA_BF16(d[0], al, bh[0], bh[1]);
            MMA_BF16(d[1], al, bh[2], bh[3]);
            MMA_BF16(d[0], ah, bl[0], bl[1]);
            MMA_BF16(d[1], ah, bl[2], bl[3]);
        }
    }

    int g = lane >> 2, t4 = lane & 3;
    int lA = (wid >> 1) * 16 + g, lB = lA + 8;
    int rA = r0 + lA, rB = r0 + lB;
    int nbase = (wid & 1) * 16;
    float psA = 0.f, pdA = 0.f, psB = 0.f, pdB = 0.f;
#pragma unroll
    for (int nt = 0; nt < 2; nt++) {
        int n0 = nbase + nt * 8 + 2 * t4;
        float w0s = s_as[n0], w1s = s_as[n0 + 1];
        float w0d = s_ad[n0], w1d = s_ad[n0 + 1];
        psA = fmaf(d[nt][0], w0s, fmaf(d[nt][1], w1s, psA));
        pdA = fmaf(d[nt][0], w0d, fmaf(d[nt][1], w1d, pdA));
        psB = fmaf(d[nt][2], w0s, fmaf(d[nt][3], w1s, psB));
        pdB = fmaf(d[nt][2], w0d, fmaf(d[nt][3], w1d, pdB));
        if (rA < N) *(float2*)&g_h2[(size_t)rA * 32 + n0] = make_float2(d[nt][0], d[nt][1]);
        if (rB < N) *(float2*)&g_h2[(size_t)rB * 32 + n0] = make_float2(d[nt][2], d[nt][3]);
    }
    psA += __shfl_xor_sync(0xffffffffu, psA, 1);
    pdA += __shfl_xor_sync(0xffffffffu, pdA, 1);
    psB += __shfl_xor_sync(0xffffffffu, psB, 1);
    pdB += __shfl_xor_sync(0xffffffffu, pdB, 1);
    psA += __shfl_xor_sync(0xffffffffu, psA, 2);
    pdA += __shfl_xor_sync(0xffffffffu, pdA, 2);
    psB += __shfl_xor_sync(0xffffffffu, psB, 2);
    pdB += __shfl_xor_sync(0xffffffffu, pdB, 2);
    if (t4 == 0) {
        int nh = wid & 1;
        ps_part[lA * 2 + nh] = psA;  pd_part[lA * 2 + nh] = pdA;
        ps_part[lB * 2 + nh] = psB;  pd_part[lB * 2 + nh] = pdB;
    }
    __syncthreads();
    if (t < 64) {
        int gr = r0 + t;
        if (gr < N) {
            g_as2[gr] = ps_part[t * 2] + ps_part[t * 2 + 1];
            g_ad2[gr] = pd_part[t * 2] + pd_part[t * 2 + 1];
        }
    }
}

// ---------------- GAT1 gather: warp per dst node (unroll 8 for MLP) ----------
__global__ __launch_bounds__(256) void k_gat1(
    const float* __restrict__ b1,
    const float* __restrict__ bg, const float* __restrict__ bb,
    const float* __restrict__ bm, const float* __restrict__ bv, int N)
{
    int gw   = (blockIdx.x * blockDim.x + threadIdx.x) >> 5;
    int lane = threadIdx.x & 31;
    if (gw >= N) return;
    int d    = gw;
    int head = lane >> 3;

    float adv = __ldg(&g_ad1[d * 4 + head]);

    float ts = __ldg(&g_as1[d * 4 + head]) + adv;
    float wself = __expf(fmaxf(ts, NEG_SLOPE * ts));
    const char* h1b  = (const char*)g_h1 + lane * 16;
    const char* as1b = (const char*)g_as1 + head * 4;
    float4 hv = *(const float4*)(h1b + ((size_t)d << 9));
    float4 acc = make_float4(wself*hv.x, wself*hv.y, wself*hv.z, wself*hv.w);
    float wsum = wself;

    int deg = min(g_deg[d], CAP);
    const int* lst = &g_csr[d * CAP];
    for (int j0 = 0; j0 < deg; j0 += 32) {
        int sid = (j0 + lane < deg) ? lst[j0 + lane] : 0;
        int soff = sid << 9;                 // byte offset into g_h1
        int m = min(32, deg - j0);
#pragma unroll 8
        for (int jj = 0; jj < m; jj++) {
            int off = __shfl_sync(0xffffffffu, soff, jj);
            float av = __ldg((const float*)(as1b + ((unsigned)off >> 5)));
            float tt = av + adv;
            float we = __expf(fmaxf(tt, NEG_SLOPE * tt));
            float4 h = *(const float4*)(h1b + off);
            acc.x = fmaf(we, h.x, acc.x);
            acc.y = fmaf(we, h.y, acc.y);
            acc.z = fmaf(we, h.z, acc.z);
            acc.w = fmaf(we, h.w, acc.w);
            wsum += we;
        }
    }

    float inv = 1.f / wsum;
    float4 bc = *(const float4*)&b1[lane * 4];
    float4 g4 = *(const float4*)&bg[lane * 4];
    float4 b4 = *(const float4*)&bb[lane * 4];
    float4 m4 = *(const float4*)&bm[lane * 4];
    float4 v4 = *(const float4*)&bv[lane * 4];
    float4 o;
    o.x = (acc.x * inv + bc.x - m4.x) * rsqrtf(v4.x + BN_EPS) * g4.x + b4.x;
    o.y = (acc.y * inv + bc.y - m4.y) * rsqrtf(v4.y + BN_EPS) * g4.y + b4.y;
    o.z = (acc.z * inv + bc.z - m4.z) * rsqrtf(v4.z + BN_EPS) * g4.z + b4.z;
    o.w = (acc.w * inv + bc.w - m4.w) * rsqrtf(v4.w + BN_EPS) * g4.w + b4.w;
    o.x = o.x > 0.f ? o.x : expm1f(o.x);
    o.y = o.y > 0.f ? o.y : expm1f(o.y);
    o.z = o.z > 0.f ? o.z : expm1f(o.z);
    o.w = o.w > 0.f ? o.w : expm1f(o.w);
    *(float4*)&g_h1p[(size_t)d * 128 + lane * 4] = o;
}

// ---------------- GAT2 gather: warp per dst node (C=32, 1 head) --------------
__global__ __launch_bounds__(256) void k_gat2(const float* __restrict__ b2, int N) {
    int gw   = (blockIdx.x * blockDim.x + threadIdx.x) >> 5;
    int lane = threadIdx.x & 31;
    if (gw >= N) return;
    int d = gw;

    float adv = __ldg(&g_ad2[d]);
    float ts = __ldg(&g_as2[d]) + adv;
    float w = __expf(fmaxf(ts, NEG_SLOPE * ts));
    const char* h2b = (const char*)g_h2 + lane * 4;
    float acc = w * *(const float*)(h2b + ((size_t)d << 7));
    float wsum = w;

    int deg = min(g_deg[d], CAP);
    const int* lst = &g_csr[d * CAP];
    for (int j0 = 0; j0 < deg; j0 += 32) {
        int m = min(32, deg - j0);
        int sid = (lane < m) ? lst[j0 + lane] : 0;
        int soff = sid << 7;
        float tt = __ldg(&g_as2[sid]) + adv;
        float wl = (lane < m) ? __expf(fmaxf(tt, NEG_SLOPE * tt)) : 0.f;
#pragma unroll 8
        for (int jj = 0; jj < m; jj++) {
            int off  = __shfl_sync(0xffffffffu, soff, jj);
            float we = __shfl_sync(0xffffffffu, wl, jj);
            acc = fmaf(we, *(const float*)(h2b + off), acc);
            wsum += we;
        }
    }
    g_o2[(size_t)d * 32 + lane] = acc / wsum + __ldg(&b2[lane]);
    if (lane == 0) g_deg[d] = 0;
}

// ---------------- final: per-node MLP tail + log_softmax ---------------------
__global__ void k_final(const float* __restrict__ ctx,
                        const float* __restrict__ rw1, const float* __restrict__ rb1,
                        const float* __restrict__ rw2, const float* __restrict__ rb2,
                        const float* __restrict__ dw,  const float* __restrict__ db,
                        const float* __restrict__ cw,  const float* __restrict__ cb,
                        float* __restrict__ out, int N) {
    __shared__ float sw[2666];
    int t = threadIdx.x;
    for (int i = t; i < 192;  i += 256) sw[i]        = rw1[i];
    for (int i = t; i < 32;   i += 256) sw[192 + i]  = rb1[i];
    for (int i = t; i < 1024; i += 256) sw[224 + i]  = rw2[i];
    for (int i = t; i < 32;   i += 256) sw[1248 + i] = rb2[i];
    for (int i = t; i < 1024; i += 256) sw[1280 + i] = dw[i];
    for (int i = t; i < 32;   i += 256) sw[2304 + i] = db[i];
    for (int i = t; i < 320;  i += 256) sw[2336 + i] = cw[i];
    for (int i = t; i < 10;   i += 256) sw[2656 + i] = cb[i];
    __syncthreads();

    int n = blockIdx.x * 256 + t;
    if (n >= N) return;

    float c0 = ctx[n * 6 + 0], c1 = ctx[n * 6 + 1], c2 = ctx[n * 6 + 2];
    float c3 = ctx[n * 6 + 3], c4 = ctx[n * 6 + 4], c5 = ctx[n * 6 + 5];

    float t1[32];
#pragma unroll
    for (int j = 0; j < 32; j++) {
        float v = sw[192 + j];
        v = fmaf(c0, sw[0 * 32 + j], v);
        v = fmaf(c1, sw[1 * 32 + j], v);
        v = fmaf(c2, sw[2 * 32 + j], v);
        v = fmaf(c3, sw[3 * 32 + j], v);
        v = fmaf(c4, sw[4 * 32 + j], v);
        v = fmaf(c5, sw[5 * 32 + j], v);
        t1[j] = fmaxf(v, 0.f);
    }
    float ex[32];
#pragma unroll
    for (int j = 0; j < 32; j++) {
        float v = sw[1248 + j];
#pragma unroll
        for (int k = 0; k < 32; k++) v = fmaf(t1[k], sw[224 + k * 32 + j], v);
        ex[j] = v;
    }
    float comb[32];
#pragma unroll
    for (int j = 0; j < 32; j++) {
        float rec = sw[2304 + j];
#pragma unroll
        for (int k = 0; k < 32; k++) rec = fmaf(ex[k], sw[1280 + k * 32 + j], rec);
        comb[j] = g_o2[(size_t)n * 32 + j] + RECON_W * rec;
    }
    float lg[10];
#pragma unroll
    for (int c = 0; c < 10; c++) {
        float v = sw[2656 + c];
#pragma unroll
        for (int j = 0; j < 32; j++) v = fmaf(comb[j], sw[2336 + j * 10 + c], v);
        lg[c] = v;
    }
    float m = lg[0];
#pragma unroll
    for (int c = 1; c < 10; c++) m = fmaxf(m, lg[c]);
    float sum = 0.f;
#pragma unroll
    for (int c = 0; c < 10; c++) sum += expf(lg[c] - m);
    float lse = m + logf(sum);
#pragma unroll
    for (int c = 0; c < 10; c++) out[n * 10 + c] = lg[c] - lse;
#pragma unroll
    for (int j = 0; j < 32; j++) out[N * 10 + n * 32 + j] = ex[j];
}

// ---------------- launch ------------------------------------------------------
extern "C" void kernel_launch(void* const* d_in, const int* in_sizes, int n_in,
                              void* d_out, int out_size) {
    const float* x    = (const float*)d_in[0];
    const int*   ei   = (const int*)  d_in[1];
    const float* ctx  = (const float*)d_in[2];
    const float* W1   = (const float*)d_in[3];
    const float* as1  = (const float*)d_in[4];
    const float* ad1  = (const float*)d_in[5];
    const float* b1   = (const float*)d_in[6];
    const float* bng  = (const float*)d_in[7];
    const float* bnb  = (const float*)d_in[8];
    const float* bnm  = (const float*)d_in[9];
    const float* bnv  = (const float*)d_in[10];
    const float* W2   = (const float*)d_in[11];
    const float* as2  = (const float*)d_in[12];
    const float* ad2  = (const float*)d_in[13];
    const float* b2   = (const float*)d_in[14];
    const float* rw1  = (const float*)d_in[15];
    const float* rb1  = (const float*)d_in[16];
    const float* rw2  = (const float*)d_in[17];
    const float* rb2  = (const float*)d_in[18];
    const float* dw   = (const float*)d_in[19];
    const float* db   = (const float*)d_in[20];
    const float* cw   = (const float*)d_in[21];
    const float* cb   = (const float*)d_in[22];
    float* out = (float*)d_out;

    int N = in_sizes[0] / 128;
    int E = in_sizes[1] / 2;

    static bool attr_set = false;
    if (!attr_set) {
        cudaFuncSetAttribute(k_gemm1_hmma, cudaFuncAttributeMaxDynamicSharedMemorySize, SM_TOT);
        cudaFuncSetAttribute(k_gemm2_hmma, cudaFuncAttributeMaxDynamicSharedMemorySize, SM2_TOT);
        attr_set = true;
    }

    // W prep (tiny), then GEMM1 with overlapped edge fill in tail blocks
    k_prep_w<<<80, 256>>>(W1, W2);
    int nb1 = (N + 127) / 128;
    int nbf = (E + 255) / 256;
    k_gemm1_hmma<<<nb1 + nbf, 256, SM_TOT>>>(x, as1, ad1, ei, N, E, nb1);
    k_gat1<<<(N * 32 + 255) / 256, 256>>>(b1, bng, bnb, bnm, bnv, N);

    // layer 2
    k_gemm2_hmma<<<(N + 63) / 64, 256, SM2_TOT>>>(as2, ad2, N);
    k_gat2<<<(N * 32 + 255) / 256, 256>>>(b2, N);

    k_final<<<(N + 255) / 256, 256>>>(ctx, rw1, rb1, rw2, rb2, dw, db, cw, cb,
                                      out, N);
}